// round 1
// baseline (speedup 1.0000x reference)
#include <cuda_runtime.h>
#include <math.h>

// Problem constants
//  x[128,256,256], W_enc[256,512], b_enc[512], WQ/WK/WV[8,512,512], n_agents=64
//  out[128,64,512] fp32
//
// Restructured computation (all fp32):
//  h   = lrelu(x) @ W_enc + b          [32768,512]
//  M_n = (WQ_n @ WK_n^T) * 1/sqrt(512) [8,512,512]
//  Q'  = ha @ M_n                      [8, 8192, 512]   (ha = agent rows of h)
//  S   = Q'_{n,b} @ h_b^T  -> softmax -> prob [8,128,64,256]
//  u   = prob_{n,b} @ h_b              stored [b,a,n,512] = [8192,4096]
//  out = (1/8) * u @ WVcat             [8192,512]

#define B_ 128
#define E_ 256
#define A_ 64
#define H_ 512
#define NH_ 8

static __device__ float g_h[32768u * 512u];          // 64 MB
static __device__ float g_M[8u * 512u * 512u];       // 8 MB
static __device__ float g_Qp[8u * 8192u * 512u];     // 67 MB
static __device__ float g_prob[8u * 128u * 64u * 256u]; // 67 MB
static __device__ float g_u[8192u * 4096u];          // 134 MB

__device__ __forceinline__ float lrelu(float v) { return v > 0.0f ? v : 0.01f * v; }

// ---------------------------------------------------------------------------
// Kernel 1: h = lrelu(x) @ W_enc + b    M=32768 N=512 K=256  (NN)
// ---------------------------------------------------------------------------
__global__ __launch_bounds__(256) void k_encode(const float* __restrict__ X,
                                                const float* __restrict__ W,
                                                const float* __restrict__ bias) {
    __shared__ float As[8][128];
    __shared__ float Bs[8][128];
    const int tid = threadIdx.x;
    const int bn = blockIdx.x, bm = blockIdx.y;
    const int ty = tid >> 4, tx = tid & 15;
    const int arow = tid >> 1, acol = (tid & 1) * 4;
    const int brow = tid >> 5, bcol = (tid & 31) * 4;

    const float* Ap = X + (size_t)(bm * 128 + arow) * 256 + acol;
    const float* Bp = W + (size_t)brow * 512 + bn * 128 + bcol;

    float acc[8][8];
#pragma unroll
    for (int i = 0; i < 8; i++)
#pragma unroll
        for (int j = 0; j < 8; j++) acc[i][j] = 0.0f;

    float4 a_n = *(const float4*)Ap;
    float4 b_n = *(const float4*)Bp;

    for (int ko = 0; ko < 256; ko += 8) {
        As[acol + 0][arow] = lrelu(a_n.x);
        As[acol + 1][arow] = lrelu(a_n.y);
        As[acol + 2][arow] = lrelu(a_n.z);
        As[acol + 3][arow] = lrelu(a_n.w);
        *(float4*)&Bs[brow][bcol] = b_n;
        __syncthreads();
        if (ko + 8 < 256) {
            a_n = *(const float4*)(Ap + ko + 8);
            b_n = *(const float4*)(Bp + (size_t)(ko + 8) * 512);
        }
#pragma unroll
        for (int kk = 0; kk < 8; kk++) {
            float a[8], b[8];
#pragma unroll
            for (int i = 0; i < 8; i++) a[i] = As[kk][ty * 8 + i];
#pragma unroll
            for (int j = 0; j < 8; j++) b[j] = Bs[kk][tx * 8 + j];
#pragma unroll
            for (int i = 0; i < 8; i++)
#pragma unroll
                for (int j = 0; j < 8; j++) acc[i][j] += a[i] * b[j];
        }
        __syncthreads();
    }
    const int row0 = bm * 128 + ty * 8;
    const int col0 = bn * 128 + tx * 8;
    float bv[8];
#pragma unroll
    for (int j = 0; j < 8; j++) bv[j] = bias[col0 + j];
#pragma unroll
    for (int i = 0; i < 8; i++) {
        float4 o0 = make_float4(acc[i][0] + bv[0], acc[i][1] + bv[1], acc[i][2] + bv[2], acc[i][3] + bv[3]);
        float4 o1 = make_float4(acc[i][4] + bv[4], acc[i][5] + bv[5], acc[i][6] + bv[6], acc[i][7] + bv[7]);
        float* dst = g_h + (size_t)(row0 + i) * 512 + col0;
        *(float4*)dst = o0;
        *(float4*)(dst + 4) = o1;
    }
}

// ---------------------------------------------------------------------------
// Kernel 2: M_n = (WQ_n @ WK_n^T) * scale    M=N=K=512 (NT), batch 8
// ---------------------------------------------------------------------------
__global__ __launch_bounds__(256) void k_wqwk(const float* __restrict__ WQ,
                                              const float* __restrict__ WK) {
    __shared__ float As[8][128];
    __shared__ float Bs[8][128];
    const int n = blockIdx.z;
    const int tid = threadIdx.x;
    const int bn = blockIdx.x, bm = blockIdx.y;
    const int ty = tid >> 4, tx = tid & 15;
    const int arow = tid >> 1, acol = (tid & 1) * 4;

    const float* Ap = WQ + (size_t)n * 512 * 512 + (size_t)(bm * 128 + arow) * 512 + acol;
    const float* Bp = WK + (size_t)n * 512 * 512 + (size_t)(bn * 128 + arow) * 512 + acol;

    float acc[8][8];
#pragma unroll
    for (int i = 0; i < 8; i++)
#pragma unroll
        for (int j = 0; j < 8; j++) acc[i][j] = 0.0f;

    float4 a_n = *(const float4*)Ap;
    float4 b_n = *(const float4*)Bp;

    for (int ko = 0; ko < 512; ko += 8) {
        As[acol + 0][arow] = a_n.x;
        As[acol + 1][arow] = a_n.y;
        As[acol + 2][arow] = a_n.z;
        As[acol + 3][arow] = a_n.w;
        Bs[acol + 0][arow] = b_n.x;
        Bs[acol + 1][arow] = b_n.y;
        Bs[acol + 2][arow] = b_n.z;
        Bs[acol + 3][arow] = b_n.w;
        __syncthreads();
        if (ko + 8 < 512) {
            a_n = *(const float4*)(Ap + ko + 8);
            b_n = *(const float4*)(Bp + ko + 8);
        }
#pragma unroll
        for (int kk = 0; kk < 8; kk++) {
            float a[8], b[8];
#pragma unroll
            for (int i = 0; i < 8; i++) a[i] = As[kk][ty * 8 + i];
#pragma unroll
            for (int j = 0; j < 8; j++) b[j] = Bs[kk][tx * 8 + j];
#pragma unroll
            for (int i = 0; i < 8; i++)
#pragma unroll
                for (int j = 0; j < 8; j++) acc[i][j] += a[i] * b[j];
        }
        __syncthreads();
    }
    const float scale = 0.04419417382415922f;  // 1/sqrt(512)
    float* C = g_M + (size_t)n * 512 * 512;
    const int row0 = bm * 128 + ty * 8;
    const int col0 = bn * 128 + tx * 8;
#pragma unroll
    for (int i = 0; i < 8; i++) {
        float4 o0 = make_float4(acc[i][0] * scale, acc[i][1] * scale, acc[i][2] * scale, acc[i][3] * scale);
        float4 o1 = make_float4(acc[i][4] * scale, acc[i][5] * scale, acc[i][6] * scale, acc[i][7] * scale);
        float* dst = C + (size_t)(row0 + i) * 512 + col0;
        *(float4*)dst = o0;
        *(float4*)(dst + 4) = o1;
    }
}

// ---------------------------------------------------------------------------
// Kernel 3: Q'_n = ha @ M_n    M=8192 N=512 K=512 (NN), batch 8, gathered A rows
// ---------------------------------------------------------------------------
__global__ __launch_bounds__(256) void k_qprime() {
    __shared__ float As[8][128];
    __shared__ float Bs[8][128];
    const int n = blockIdx.z;
    const int tid = threadIdx.x;
    const int bn = blockIdx.x, bm = blockIdx.y;
    const int ty = tid >> 4, tx = tid & 15;
    const int arow = tid >> 1, acol = (tid & 1) * 4;
    const int brow = tid >> 5, bcol = (tid & 31) * 4;

    const int g = bm * 128 + arow;                 // global Q' row
    const int hrow = ((g >> 6) << 8) + (g & 63);   // b*256 + a
    const float* Ap = g_h + (size_t)hrow * 512 + acol;
    const float* Bp = g_M + (size_t)n * 512 * 512 + (size_t)brow * 512 + bn * 128 + bcol;

    float acc[8][8];
#pragma unroll
    for (int i = 0; i < 8; i++)
#pragma unroll
        for (int j = 0; j < 8; j++) acc[i][j] = 0.0f;

    float4 a_n = *(const float4*)Ap;
    float4 b_n = *(const float4*)Bp;

    for (int ko = 0; ko < 512; ko += 8) {
        As[acol + 0][arow] = a_n.x;
        As[acol + 1][arow] = a_n.y;
        As[acol + 2][arow] = a_n.z;
        As[acol + 3][arow] = a_n.w;
        *(float4*)&Bs[brow][bcol] = b_n;
        __syncthreads();
        if (ko + 8 < 512) {
            a_n = *(const float4*)(Ap + ko + 8);
            b_n = *(const float4*)(Bp + (size_t)(ko + 8) * 512);
        }
#pragma unroll
        for (int kk = 0; kk < 8; kk++) {
            float a[8], b[8];
#pragma unroll
            for (int i = 0; i < 8; i++) a[i] = As[kk][ty * 8 + i];
#pragma unroll
            for (int j = 0; j < 8; j++) b[j] = Bs[kk][tx * 8 + j];
#pragma unroll
            for (int i = 0; i < 8; i++)
#pragma unroll
                for (int j = 0; j < 8; j++) acc[i][j] += a[i] * b[j];
        }
        __syncthreads();
    }
    float* C = g_Qp + (size_t)n * 8192 * 512;
    const int row0 = bm * 128 + ty * 8;
    const int col0 = bn * 128 + tx * 8;
#pragma unroll
    for (int i = 0; i < 8; i++) {
        float4 o0 = make_float4(acc[i][0], acc[i][1], acc[i][2], acc[i][3]);
        float4 o1 = make_float4(acc[i][4], acc[i][5], acc[i][6], acc[i][7]);
        float* dst = C + (size_t)(row0 + i) * 512 + col0;
        *(float4*)dst = o0;
        *(float4*)(dst + 4) = o1;
    }
}

// ---------------------------------------------------------------------------
// Kernel 4: per (n,b): S = Q'[64,512] @ h_b^T[512,256] -> softmax -> prob
//           one CTA computes the whole 64x256 tile (8x8 per thread).
//           warp w owns rows w*8..w*8+7 -> shuffle softmax.
// ---------------------------------------------------------------------------
__global__ __launch_bounds__(256) void k_scores() {
    __shared__ float As[8][64];
    __shared__ float Bs[8][256];
    const int b = blockIdx.x, n = blockIdx.y;
    const int tid = threadIdx.x;
    const int ty = tid >> 5;   // warp id = row group
    const int tx = tid & 31;   // lane = col group

    const float* A = g_Qp + ((size_t)n * 8192 + (size_t)b * 64) * 512;
    const float* B = g_h + (size_t)b * 256 * 512;

    const int arow = tid >> 1, acol = (tid & 1) * 4;
    const float* Ap = A + (size_t)arow * 512 + acol;
    const float* Bp = B + (size_t)tid * 512;

    float acc[8][8];
#pragma unroll
    for (int i = 0; i < 8; i++)
#pragma unroll
        for (int j = 0; j < 8; j++) acc[i][j] = 0.0f;

    float4 a_n = make_float4(0.f, 0.f, 0.f, 0.f);
    if (tid < 128) a_n = *(const float4*)Ap;
    float4 b_n0 = *(const float4*)Bp;
    float4 b_n1 = *(const float4*)(Bp + 4);

    for (int ko = 0; ko < 512; ko += 8) {
        if (tid < 128) {
            As[acol + 0][arow] = a_n.x;
            As[acol + 1][arow] = a_n.y;
            As[acol + 2][arow] = a_n.z;
            As[acol + 3][arow] = a_n.w;
        }
        Bs[0][tid] = b_n0.x; Bs[1][tid] = b_n0.y; Bs[2][tid] = b_n0.z; Bs[3][tid] = b_n0.w;
        Bs[4][tid] = b_n1.x; Bs[5][tid] = b_n1.y; Bs[6][tid] = b_n1.z; Bs[7][tid] = b_n1.w;
        __syncthreads();
        if (ko + 8 < 512) {
            if (tid < 128) a_n = *(const float4*)(Ap + ko + 8);
            b_n0 = *(const float4*)(Bp + ko + 8);
            b_n1 = *(const float4*)(Bp + ko + 12);
        }
#pragma unroll
        for (int kk = 0; kk < 8; kk++) {
            float a[8], bb[8];
#pragma unroll
            for (int i = 0; i < 8; i++) a[i] = As[kk][ty * 8 + i];
#pragma unroll
            for (int j = 0; j < 8; j++) bb[j] = Bs[kk][tx * 8 + j];
#pragma unroll
            for (int i = 0; i < 8; i++)
#pragma unroll
                for (int j = 0; j < 8; j++) acc[i][j] += a[i] * bb[j];
        }
        __syncthreads();
    }

    // softmax per row; each warp has 8 rows, row spread across 32 lanes x 8 cols
    float* P = g_prob + (((size_t)n * 128 + b) * 64) * 256;
#pragma unroll
    for (int i = 0; i < 8; i++) {
        float m = -1e30f;
#pragma unroll
        for (int j = 0; j < 8; j++) m = fmaxf(m, acc[i][j]);
#pragma unroll
        for (int off = 16; off > 0; off >>= 1)
            m = fmaxf(m, __shfl_xor_sync(0xffffffffu, m, off));
        float s = 0.0f;
#pragma unroll
        for (int j = 0; j < 8; j++) {
            acc[i][j] = __expf(acc[i][j] - m);
            s += acc[i][j];
        }
#pragma unroll
        for (int off = 16; off > 0; off >>= 1)
            s += __shfl_xor_sync(0xffffffffu, s, off);
        const float inv = 1.0f / s;
        float4 o0 = make_float4(acc[i][0] * inv, acc[i][1] * inv, acc[i][2] * inv, acc[i][3] * inv);
        float4 o1 = make_float4(acc[i][4] * inv, acc[i][5] * inv, acc[i][6] * inv, acc[i][7] * inv);
        float* dst = P + (size_t)(ty * 8 + i) * 256 + tx * 8;
        *(float4*)dst = o0;
        *(float4*)(dst + 4) = o1;
    }
}

// ---------------------------------------------------------------------------
// Kernel 5: per (n,b,dtile): u = prob[64,256] @ h_b[256, dtile*128..]
//           M=64 N=128 K=256. Output layout g_u[b,a,n,512].
// ---------------------------------------------------------------------------
__global__ __launch_bounds__(256) void k_attnv() {
    __shared__ float As[8][64];
    __shared__ float Bs[8][128];
    const int bn = blockIdx.x, b = blockIdx.y, n = blockIdx.z;
    const int tid = threadIdx.x;
    const int ty = tid >> 4, tx = tid & 15;   // micro 4x8: rows ty*4, cols tx*8

    const float* A = g_prob + ((size_t)n * 128 + b) * 64 * 256;
    const float* B = g_h + (size_t)b * 256 * 512 + bn * 128;

    const int arow = tid >> 1, acol = (tid & 1) * 4;
    const int brow = tid >> 5, bcol = (tid & 31) * 4;
    const float* Ap = A + (size_t)arow * 256 + acol;
    const float* Bp = B + (size_t)brow * 512 + bcol;

    float acc[4][8];
#pragma unroll
    for (int i = 0; i < 4; i++)
#pragma unroll
        for (int j = 0; j < 8; j++) acc[i][j] = 0.0f;

    float4 a_n = make_float4(0.f, 0.f, 0.f, 0.f);
    if (tid < 128) a_n = *(const float4*)Ap;
    float4 b_n = *(const float4*)Bp;

    for (int ko = 0; ko < 256; ko += 8) {
        if (tid < 128) {
            As[acol + 0][arow] = a_n.x;
            As[acol + 1][arow] = a_n.y;
            As[acol + 2][arow] = a_n.z;
            As[acol + 3][arow] = a_n.w;
        }
        *(float4*)&Bs[brow][bcol] = b_n;
        __syncthreads();
        if (ko + 8 < 256) {
            if (tid < 128) a_n = *(const float4*)(Ap + ko + 8);
            b_n = *(const float4*)(Bp + (size_t)(ko + 8) * 512);
        }
#pragma unroll
        for (int kk = 0; kk < 8; kk++) {
            float a[4], bb[8];
#pragma unroll
            for (int i = 0; i < 4; i++) a[i] = As[kk][ty * 4 + i];
#pragma unroll
            for (int j = 0; j < 8; j++) bb[j] = Bs[kk][tx * 8 + j];
#pragma unroll
            for (int i = 0; i < 4; i++)
#pragma unroll
                for (int j = 0; j < 8; j++) acc[i][j] += a[i] * bb[j];
        }
        __syncthreads();
    }
#pragma unroll
    for (int i = 0; i < 4; i++) {
        const int a_local = ty * 4 + i;  // agent index 0..63
        float* dst = g_u + (((size_t)(b * 64 + a_local)) * 8 + n) * 512 + bn * 128 + tx * 8;
        float4 o0 = make_float4(acc[i][0], acc[i][1], acc[i][2], acc[i][3]);
        float4 o1 = make_float4(acc[i][4], acc[i][5], acc[i][6], acc[i][7]);
        *(float4*)dst = o0;
        *(float4*)(dst + 4) = o1;
    }
}

// ---------------------------------------------------------------------------
// Kernel 6: out = (1/8) * g_u @ WVcat    M=8192 N=512 K=4096 (NN)
// ---------------------------------------------------------------------------
__global__ __launch_bounds__(256) void k_out(float* __restrict__ out,
                                             const float* __restrict__ WV) {
    __shared__ float As[8][128];
    __shared__ float Bs[8][128];
    const int tid = threadIdx.x;
    const int bn = blockIdx.x, bm = blockIdx.y;
    const int ty = tid >> 4, tx = tid & 15;
    const int arow = tid >> 1, acol = (tid & 1) * 4;
    const int brow = tid >> 5, bcol = (tid & 31) * 4;

    const float* Ap = g_u + (size_t)(bm * 128 + arow) * 4096 + acol;
    const float* Bp = WV + (size_t)brow * 512 + bn * 128 + bcol;

    float acc[8][8];
#pragma unroll
    for (int i = 0; i < 8; i++)
#pragma unroll
        for (int j = 0; j < 8; j++) acc[i][j] = 0.0f;

    float4 a_n = *(const float4*)Ap;
    float4 b_n = *(const float4*)Bp;

    for (int ko = 0; ko < 4096; ko += 8) {
        As[acol + 0][arow] = a_n.x;
        As[acol + 1][arow] = a_n.y;
        As[acol + 2][arow] = a_n.z;
        As[acol + 3][arow] = a_n.w;
        *(float4*)&Bs[brow][bcol] = b_n;
        __syncthreads();
        if (ko + 8 < 4096) {
            a_n = *(const float4*)(Ap + ko + 8);
            b_n = *(const float4*)(Bp + (size_t)(ko + 8) * 512);
        }
#pragma unroll
        for (int kk = 0; kk < 8; kk++) {
            float a[8], b[8];
#pragma unroll
            for (int i = 0; i < 8; i++) a[i] = As[kk][ty * 8 + i];
#pragma unroll
            for (int j = 0; j < 8; j++) b[j] = Bs[kk][tx * 8 + j];
#pragma unroll
            for (int i = 0; i < 8; i++)
#pragma unroll
                for (int j = 0; j < 8; j++) acc[i][j] += a[i] * b[j];
        }
        __syncthreads();
    }
    const int row0 = bm * 128 + ty * 8;
    const int col0 = bn * 128 + tx * 8;
#pragma unroll
    for (int i = 0; i < 8; i++) {
        float4 o0 = make_float4(acc[i][0] * 0.125f, acc[i][1] * 0.125f, acc[i][2] * 0.125f, acc[i][3] * 0.125f);
        float4 o1 = make_float4(acc[i][4] * 0.125f, acc[i][5] * 0.125f, acc[i][6] * 0.125f, acc[i][7] * 0.125f);
        float* dst = out + (size_t)(row0 + i) * 512 + col0;
        *(float4*)dst = o0;
        *(float4*)(dst + 4) = o1;
    }
}

// ---------------------------------------------------------------------------
extern "C" void kernel_launch(void* const* d_in, const int* in_sizes, int n_in,
                              void* d_out, int out_size) {
    const float* x     = (const float*)d_in[0];
    const float* W_enc = (const float*)d_in[1];
    const float* b_enc = (const float*)d_in[2];
    const float* WQ    = (const float*)d_in[3];
    const float* WK    = (const float*)d_in[4];
    const float* WV    = (const float*)d_in[5];
    float* out = (float*)d_out;

    k_encode<<<dim3(4, 256), 256>>>(x, W_enc, b_enc);
    k_wqwk<<<dim3(4, 4, 8), 256>>>(WQ, WK);
    k_qprime<<<dim3(4, 64, 8), 256>>>();
    k_scores<<<dim3(128, 8), 256>>>();
    k_attnv<<<dim3(4, 128, 8), 256>>>();
    k_out<<<dim3(4, 64), 256>>>(out, WV);
}

// round 5
// speedup vs baseline: 2.1789x; 2.1789x over previous
#include <cuda_runtime.h>
#include <cuda_fp16.h>
#include <mma.h>
#include <cstdint>
#include <string.h>
#include <math.h>
#include <type_traits>

using namespace nvcuda;

// ===========================================================================
//  h   = lrelu(x) @ W_enc + b            [32768,512]   (WMMA fp16x2-split)
//  M_n = (WQ_n @ WK_n^T) / sqrt(512)     [8,512,512]   (FFMA fp32)
//  Q'  = ha @ M_n                        [8,8192,512]  (WMMA)
//  S   = Q' @ h^T                        [8,128,64,256](WMMA) -> softmax
//  u   = prob @ h    -> [b,a,n*512+d]    (WMMA)
//  out = (1/8) u @ WVcat                 [8192,512]    (WMMA)
// All WMMA GEMMs: operands as fp16 (hi,lo) split pairs, 3 products
// (a0b0 + a0b1 + a1b0) -> ~22-bit effective precision, fp32 accumulate.
// ===========================================================================

// -------------------- scratch (device globals) -----------------------------
static __device__ float  g_M [8u * 512u * 512u];
static __device__ float  g_S [8u * 128u * 64u * 256u];      // scores fp32
static __device__ __half g_h0[32768u * 512u],  g_h1[32768u * 512u];
static __device__ __half g_Q0[8u * 8192u * 512u], g_Q1[8u * 8192u * 512u];
static __device__ __half g_P0[8u * 128u * 64u * 256u], g_P1[8u * 128u * 64u * 256u];
static __device__ __half g_U0[8192u * 4096u], g_U1[8192u * 4096u];
static __device__ __half g_Te0[512u * 256u],  g_Te1[512u * 256u];        // W_enc^T
static __device__ __half g_Tm0[8u * 512u * 512u], g_Tm1[8u * 512u * 512u]; // M^T
static __device__ __half g_Tw0[512u * 4096u], g_Tw1[512u * 4096u];       // WVcat^T

__device__ __forceinline__ float lrelu(float v) { return v > 0.0f ? v : 0.01f * v; }

__device__ __forceinline__ void split2(float v, __half& h0, __half& h1) {
    h0 = __float2half_rn(v);
    h1 = __float2half_rn(v - __half2float(h0));
}

__device__ __forceinline__ uint32_t h2u(__half2 v) {
    uint32_t u;
    memcpy(&u, &v, 4);
    return u;
}

// ---------------------------------------------------------------------------
// transpose + fp16 split2:  T*[n*K+k] = split(B[k*N+n])
// ---------------------------------------------------------------------------
__global__ __launch_bounds__(256) void k_tsplit2(const float* __restrict__ B,
                                                 __half* __restrict__ T0,
                                                 __half* __restrict__ T1,
                                                 int K, int N) {
    const size_t total = (size_t)K * N;
    const size_t base = (size_t)blockIdx.y * total;
    for (size_t idx = (size_t)blockIdx.x * 256 + threadIdx.x; idx < total;
         idx += (size_t)gridDim.x * 256) {
        int k = (int)(idx / (unsigned)N), n = (int)(idx % (unsigned)N);
        float v = B[base + idx];
        __half a, b;
        split2(v, a, b);
        size_t o = base + (size_t)n * K + k;
        T0[o] = a;
        T1[o] = b;
    }
}

// ---------------------------------------------------------------------------
// Generic WMMA GEMM.  C[BMxBN=128] = alpha*(A@B)+bias, 3-product fp16 split.
// A: either fp32 (split in-kernel, optional lrelu / row gather) or plane pair.
// B: plane pair; BROW=false -> B stored [N,K] (col_major frags),
//                BROW=true  -> B stored [K,N] (row_major frags).
// Output: fp32 (Cf) or split-plane pair (C0g/C1g).
// Batch: z -> zlo=z&zmask, zhi=z>>zshift; off = zlo*Lo + zhi*Hi per operand.
// ---------------------------------------------------------------------------
template <int BM, bool BROW>
__global__ __launch_bounds__(256) void k_mma(
    const float* __restrict__ Afp,
    const __half* __restrict__ A0g, const __half* __restrict__ A1g,
    const __half* __restrict__ B0g, const __half* __restrict__ B1g,
    float* __restrict__ Cf, __half* __restrict__ C0g, __half* __restrict__ C1g,
    const float* __restrict__ bias, float alpha,
    int Ktot, int lda, int ldb, int ldc,
    int flags,  // 1 = lrelu on fp32 A, 2 = gather rows (b*256+a map)
    long long aLo, long long aHi, long long bLo, long long bHi,
    long long cLo, long long cHi, int zmask, int zshift)
{
    constexpr int WMG = (BM == 128) ? 4 : 2;   // warps along M
    constexpr int WNG = 8 / WMG;               // warps along N
    constexpr int WN  = 128 / WNG;             // 64 or 32
    constexpr int NF  = WN / 16;               // 4 or 2
    constexpr int LDA = 40;                    // padded half-stride
    constexpr int LDB = BROW ? 136 : 40;
    constexpr int APL = BM * LDA * 2;          // A plane bytes
    constexpr int BPL = BROW ? 32 * LDB * 2 : 128 * LDB * 2;
    constexpr int STAGE = 2 * APL + 2 * BPL;
    constexpr int ACH = BM * 4 / 256;          // A uint4 chunks per thread per plane
    constexpr int AF4 = BM * 8 / 256;          // A float4 per thread (fp32 path)

    extern __shared__ __align__(1024) char sm[];

    const int tid = threadIdx.x;
    const int w = tid >> 5;
    const int wm = w & (WMG - 1);
    const int wn = w / WMG;
    const int z = blockIdx.z;
    const int zlo = z & zmask, zhi = z >> zshift;
    const long long aoff = (long long)zlo * aLo + (long long)zhi * aHi;
    const long long boff = (long long)zlo * bLo + (long long)zhi * bHi;
    const long long coff = (long long)zlo * cLo + (long long)zhi * cHi;
    const int m0 = blockIdx.y * BM;
    const int n0 = blockIdx.x * 128;
    const bool a_fp32 = (Afp != nullptr);
    const bool gather = (flags & 2) != 0;
    const bool do_lrelu = (flags & 1) != 0;

    // ---- per-thread load coordinates
    int aprow[4], apk[4];     // plane path
    int afrow[8], afk[8];     // fp32 path
#pragma unroll
    for (int i = 0; i < ACH; i++) {
        int id = tid + i * 256;
        aprow[i] = id >> 2;
        apk[i] = (id & 3) * 8;
    }
#pragma unroll
    for (int i = 0; i < AF4; i++) {
        int id = tid + i * 256;
        afrow[i] = id >> 3;
        afk[i] = (id & 7) * 4;
    }
    int brow[2], bk[2];
#pragma unroll
    for (int i = 0; i < 2; i++) {
        int id = tid + i * 256;
        if (BROW) { brow[i] = id >> 4; bk[i] = (id & 15) * 8; }   // row=k, col=n
        else      { brow[i] = id >> 2; bk[i] = (id & 3) * 8; }    // row=n, col=k
    }

    auto a_grow = [&](int r) -> long long {
        int g = m0 + r;
        return gather ? (long long)(((g >> 6) << 8) + (g & 63)) : (long long)g;
    };

    // ---- accumulators
    wmma::fragment<wmma::accumulator, 16, 16, 16, float> acc[2][NF];
#pragma unroll
    for (int mf = 0; mf < 2; mf++)
#pragma unroll
        for (int nf = 0; nf < NF; nf++) wmma::fill_fragment(acc[mf][nf], 0.0f);

    using BLayout = typename std::conditional<BROW, wmma::row_major, wmma::col_major>::type;

    // ---- staging registers
    uint4 ra0[ACH ? ACH : 1], ra1[ACH ? ACH : 1];
    float4 rf[AF4 ? AF4 : 1];
    uint4 rb0[2], rb1[2];

    auto load_tile = [&](int k0) {
        if (a_fp32) {
#pragma unroll
            for (int i = 0; i < AF4; i++)
                rf[i] = *(const float4*)(Afp + aoff + a_grow(afrow[i]) * lda + k0 + afk[i]);
        } else {
#pragma unroll
            for (int i = 0; i < ACH; i++) {
                long long r = aoff + a_grow(aprow[i]) * lda + k0 + apk[i];
                ra0[i] = *(const uint4*)(A0g + r);
                ra1[i] = *(const uint4*)(A1g + r);
            }
        }
#pragma unroll
        for (int i = 0; i < 2; i++) {
            long long r = BROW ? (boff + (long long)(k0 + brow[i]) * ldb + n0 + bk[i])
                               : (boff + (long long)(n0 + brow[i]) * ldb + k0 + bk[i]);
            rb0[i] = *(const uint4*)(B0g + r);
            rb1[i] = *(const uint4*)(B1g + r);
        }
    };

    auto store_tile = [&](int buf) {
        char* base = sm + buf * STAGE;
        char* sA0 = base;
        char* sA1 = base + APL;
        char* sB0 = base + 2 * APL;
        char* sB1 = base + 2 * APL + BPL;
        if (a_fp32) {
#pragma unroll
            for (int i = 0; i < AF4; i++) {
                float4 v = rf[i];
                if (do_lrelu) { v.x = lrelu(v.x); v.y = lrelu(v.y); v.z = lrelu(v.z); v.w = lrelu(v.w); }
                __half x0, x1, y0, y1, z0, z1, w0, w1;
                split2(v.x, x0, x1); split2(v.y, y0, y1);
                split2(v.z, z0, z1); split2(v.w, w0, w1);
                int off = afrow[i] * (LDA * 2) + afk[i] * 2;
                __half2 p0 = __halves2half2(x0, y0), q0 = __halves2half2(z0, w0);
                __half2 p1 = __halves2half2(x1, y1), q1 = __halves2half2(z1, w1);
                *(uint2*)(sA0 + off) = make_uint2(h2u(p0), h2u(q0));
                *(uint2*)(sA1 + off) = make_uint2(h2u(p1), h2u(q1));
            }
        } else {
#pragma unroll
            for (int i = 0; i < ACH; i++) {
                int off = aprow[i] * (LDA * 2) + apk[i] * 2;
                *(uint4*)(sA0 + off) = ra0[i];
                *(uint4*)(sA1 + off) = ra1[i];
            }
        }
#pragma unroll
        for (int i = 0; i < 2; i++) {
            int off = brow[i] * (LDB * 2) + bk[i] * 2;
            *(uint4*)(sB0 + off) = rb0[i];
            *(uint4*)(sB1 + off) = rb1[i];
        }
    };

    auto mma_tile = [&](int buf) {
        const char* base = sm + buf * STAGE;
        const __half* sA0 = (const __half*)(base);
        const __half* sA1 = (const __half*)(base + APL);
        const __half* sB0 = (const __half*)(base + 2 * APL);
        const __half* sB1 = (const __half*)(base + 2 * APL + BPL);
#pragma unroll
        for (int ks = 0; ks < 32; ks += 16) {
            wmma::fragment<wmma::matrix_a, 16, 16, 16, __half, wmma::row_major> a0f[2], a1f[2];
#pragma unroll
            for (int mf = 0; mf < 2; mf++) {
                int r0 = wm * 32 + mf * 16;
                wmma::load_matrix_sync(a0f[mf], sA0 + r0 * LDA + ks, LDA);
                wmma::load_matrix_sync(a1f[mf], sA1 + r0 * LDA + ks, LDA);
            }
#pragma unroll
            for (int nf = 0; nf < NF; nf++) {
                int col = wn * WN + nf * 16;
                wmma::fragment<wmma::matrix_b, 16, 16, 16, __half, BLayout> b0f, b1f;
                const __half* pb0 = BROW ? (sB0 + ks * LDB + col) : (sB0 + col * LDB + ks);
                const __half* pb1 = BROW ? (sB1 + ks * LDB + col) : (sB1 + col * LDB + ks);
                wmma::load_matrix_sync(b0f, pb0, LDB);
                wmma::load_matrix_sync(b1f, pb1, LDB);
#pragma unroll
                for (int mf = 0; mf < 2; mf++) {
                    wmma::mma_sync(acc[mf][nf], a0f[mf], b0f, acc[mf][nf]);
                    wmma::mma_sync(acc[mf][nf], a0f[mf], b1f, acc[mf][nf]);
                    wmma::mma_sync(acc[mf][nf], a1f[mf], b0f, acc[mf][nf]);
                }
            }
        }
    };

    // ---- main double-buffered loop
    const int numK = Ktot >> 5;
    load_tile(0);
    for (int t = 0; t < numK; t++) {
        store_tile(t & 1);
        __syncthreads();
        if (t + 1 < numK) load_tile((t + 1) << 5);
        mma_tile(t & 1);
    }

    // ---- epilogue: stage C through smem (reuses operand buffers)
    __syncthreads();
    float* Csm = (float*)sm;
#pragma unroll
    for (int mf = 0; mf < 2; mf++)
#pragma unroll
        for (int nf = 0; nf < NF; nf++) {
            int r0 = wm * 32 + mf * 16, c0 = wn * WN + nf * 16;
            wmma::store_matrix_sync(Csm + r0 * 128 + c0, acc[mf][nf], 128, wmma::mem_row_major);
        }
    __syncthreads();

    const int NOUT = BM * 128 / 4 / 256;  // float4 per thread
#pragma unroll
    for (int i = 0; i < NOUT; i++) {
        int f = tid + i * 256;
        int row = f >> 5, c4 = (f & 31) * 4;
        float4 v = *(float4*)(Csm + row * 128 + c4);
        v.x *= alpha; v.y *= alpha; v.z *= alpha; v.w *= alpha;
        if (bias) {
            v.x += bias[n0 + c4 + 0]; v.y += bias[n0 + c4 + 1];
            v.z += bias[n0 + c4 + 2]; v.w += bias[n0 + c4 + 3];
        }
        long long o = coff + (long long)(m0 + row) * ldc + n0 + c4;   // FIXED: + m0
        if (Cf) {
            *(float4*)(Cf + o) = v;
        } else {
            __half x0, x1, y0, y1, z0, z1, w0, w1;
            split2(v.x, x0, x1); split2(v.y, y0, y1);
            split2(v.z, z0, z1); split2(v.w, w0, w1);
            __half2 p0 = __halves2half2(x0, y0), q0 = __halves2half2(z0, w0);
            __half2 p1 = __halves2half2(x1, y1), q1 = __halves2half2(z1, w1);
            *(uint2*)(C0g + o) = make_uint2(h2u(p0), h2u(q0));
            *(uint2*)(C1g + o) = make_uint2(h2u(p1), h2u(q1));
        }
    }
}

// ---------------------------------------------------------------------------
// M_n = (WQ_n @ WK_n^T) * scale   (FFMA fp32, small)
// ---------------------------------------------------------------------------
__global__ __launch_bounds__(256) void k_wqwk(const float* __restrict__ WQ,
                                              const float* __restrict__ WK) {
    __shared__ float As[8][128];
    __shared__ float Bs[8][128];
    const int n = blockIdx.z;
    const int tid = threadIdx.x;
    const int bn = blockIdx.x, bm = blockIdx.y;
    const int ty = tid >> 4, tx = tid & 15;
    const int arow = tid >> 1, acol = (tid & 1) * 4;

    const float* Ap = WQ + (size_t)n * 512 * 512 + (size_t)(bm * 128 + arow) * 512 + acol;
    const float* Bp = WK + (size_t)n * 512 * 512 + (size_t)(bn * 128 + arow) * 512 + acol;

    float acc[8][8];
#pragma unroll
    for (int i = 0; i < 8; i++)
#pragma unroll
        for (int j = 0; j < 8; j++) acc[i][j] = 0.0f;

    float4 a_n = *(const float4*)Ap;
    float4 b_n = *(const float4*)Bp;

    for (int ko = 0; ko < 512; ko += 8) {
        As[acol + 0][arow] = a_n.x; As[acol + 1][arow] = a_n.y;
        As[acol + 2][arow] = a_n.z; As[acol + 3][arow] = a_n.w;
        Bs[acol + 0][arow] = b_n.x; Bs[acol + 1][arow] = b_n.y;
        Bs[acol + 2][arow] = b_n.z; Bs[acol + 3][arow] = b_n.w;
        __syncthreads();
        if (ko + 8 < 512) {
            a_n = *(const float4*)(Ap + ko + 8);
            b_n = *(const float4*)(Bp + ko + 8);
        }
#pragma unroll
        for (int kk = 0; kk < 8; kk++) {
            float a[8], b[8];
#pragma unroll
            for (int i = 0; i < 8; i++) a[i] = As[kk][ty * 8 + i];
#pragma unroll
            for (int j = 0; j < 8; j++) b[j] = Bs[kk][tx * 8 + j];
#pragma unroll
            for (int i = 0; i < 8; i++)
#pragma unroll
                for (int j = 0; j < 8; j++) acc[i][j] += a[i] * b[j];
        }
        __syncthreads();
    }
    const float scale = 0.04419417382415922f;
    float* Cm = g_M + (size_t)n * 512 * 512;
    const int row0 = bm * 128 + ty * 8;
    const int col0 = bn * 128 + tx * 8;
#pragma unroll
    for (int i = 0; i < 8; i++) {
        float4 o0 = make_float4(acc[i][0] * scale, acc[i][1] * scale, acc[i][2] * scale, acc[i][3] * scale);
        float4 o1 = make_float4(acc[i][4] * scale, acc[i][5] * scale, acc[i][6] * scale, acc[i][7] * scale);
        float* dst = Cm + (size_t)(row0 + i) * 512 + col0;
        *(float4*)dst = o0;
        *(float4*)(dst + 4) = o1;
    }
}

// ---------------------------------------------------------------------------
// softmax over rows of g_S (65536 rows x 256) -> fp16 split planes g_P0/g_P1
// ---------------------------------------------------------------------------
__global__ __launch_bounds__(256) void k_softmax() {
    const int row = blockIdx.x * 8 + (threadIdx.x >> 5);
    const int lane = threadIdx.x & 31;
    const float* src = g_S + (size_t)row * 256 + lane * 8;

    float4 v0 = *(const float4*)src;
    float4 v1 = *(const float4*)(src + 4);
    float m = fmaxf(fmaxf(fmaxf(v0.x, v0.y), fmaxf(v0.z, v0.w)),
                    fmaxf(fmaxf(v1.x, v1.y), fmaxf(v1.z, v1.w)));
#pragma unroll
    for (int off = 16; off > 0; off >>= 1)
        m = fmaxf(m, __shfl_xor_sync(0xffffffffu, m, off));
    v0.x = __expf(v0.x - m); v0.y = __expf(v0.y - m);
    v0.z = __expf(v0.z - m); v0.w = __expf(v0.w - m);
    v1.x = __expf(v1.x - m); v1.y = __expf(v1.y - m);
    v1.z = __expf(v1.z - m); v1.w = __expf(v1.w - m);
    float s = v0.x + v0.y + v0.z + v0.w + v1.x + v1.y + v1.z + v1.w;
#pragma unroll
    for (int off = 16; off > 0; off >>= 1)
        s += __shfl_xor_sync(0xffffffffu, s, off);
    const float inv = 1.0f / s;
    float p[8] = {v0.x * inv, v0.y * inv, v0.z * inv, v0.w * inv,
                  v1.x * inv, v1.y * inv, v1.z * inv, v1.w * inv};
    __align__(16) __half h0[8];
    __align__(16) __half h1[8];
#pragma unroll
    for (int j = 0; j < 8; j++) split2(p[j], h0[j], h1[j]);
    size_t o = (size_t)row * 256 + lane * 8;
    *(uint4*)(g_P0 + o) = *(uint4*)h0;
    *(uint4*)(g_P1 + o) = *(uint4*)h1;
}

// ---------------------------------------------------------------------------
extern "C" void kernel_launch(void* const* d_in, const int* in_sizes, int n_in,
                              void* d_out, int out_size) {
    const float* x     = (const float*)d_in[0];
    const float* W_enc = (const float*)d_in[1];
    const float* b_enc = (const float*)d_in[2];
    const float* WQ    = (const float*)d_in[3];
    const float* WK    = (const float*)d_in[4];
    const float* WV    = (const float*)d_in[5];
    float* out = (float*)d_out;

    // smem sizes per instantiation
    const int SM128 = 2 * (2 * 128 * 40 * 2 + 2 * 128 * 40 * 2);        // 81920
    const int SM64C = 2 * (2 * 64 * 40 * 2 + 2 * 128 * 40 * 2);         // 61440
    const int SM64R = 2 * (2 * 64 * 40 * 2 + 2 * 32 * 136 * 2);         // 55296
    cudaFuncSetAttribute(k_mma<128, false>, cudaFuncAttributeMaxDynamicSharedMemorySize, SM128);
    cudaFuncSetAttribute(k_mma<64, false>, cudaFuncAttributeMaxDynamicSharedMemorySize, SM64C);
    cudaFuncSetAttribute(k_mma<64, true>, cudaFuncAttributeMaxDynamicSharedMemorySize, SM64R);

    void *p_M, *p_S, *p_h0, *p_h1, *p_Q0, *p_Q1, *p_P0, *p_P1, *p_U0, *p_U1;
    void *p_e0, *p_e1, *p_m0, *p_m1, *p_w0, *p_w1;
    cudaGetSymbolAddress(&p_M, g_M);   cudaGetSymbolAddress(&p_S, g_S);
    cudaGetSymbolAddress(&p_h0, g_h0); cudaGetSymbolAddress(&p_h1, g_h1);
    cudaGetSymbolAddress(&p_Q0, g_Q0); cudaGetSymbolAddress(&p_Q1, g_Q1);
    cudaGetSymbolAddress(&p_P0, g_P0); cudaGetSymbolAddress(&p_P1, g_P1);
    cudaGetSymbolAddress(&p_U0, g_U0); cudaGetSymbolAddress(&p_U1, g_U1);
    cudaGetSymbolAddress(&p_e0, g_Te0); cudaGetSymbolAddress(&p_e1, g_Te1);
    cudaGetSymbolAddress(&p_m0, g_Tm0); cudaGetSymbolAddress(&p_m1, g_Tm1);
    cudaGetSymbolAddress(&p_w0, g_Tw0); cudaGetSymbolAddress(&p_w1, g_Tw1);

    // ---- weight prep
    k_tsplit2<<<dim3(128, 1), 256>>>(W_enc, (__half*)p_e0, (__half*)p_e1, 256, 512);
    k_tsplit2<<<dim3(1024, 1), 256>>>(WV, (__half*)p_w0, (__half*)p_w1, 4096, 512);
    k_wqwk<<<dim3(4, 4, 8), 256>>>(WQ, WK);
    k_tsplit2<<<dim3(256, 8), 256>>>((const float*)p_M, (__half*)p_m0, (__half*)p_m1, 512, 512);

    // ---- encode: h planes = lrelu(x) @ W_enc + b
    k_mma<128, false><<<dim3(4, 256, 1), 256, SM128>>>(
        x, nullptr, nullptr, (const __half*)p_e0, (const __half*)p_e1,
        nullptr, (__half*)p_h0, (__half*)p_h1, b_enc, 1.0f,
        /*K*/256, /*lda*/256, /*ldb*/256, /*ldc*/512, /*flags*/1,
        0, 0, 0, 0, 0, 0, 0, 0);

    // ---- Q' planes = ha @ M_n   (gather, batched over heads via zhi)
    k_mma<128, false><<<dim3(4, 64, 8), 256, SM128>>>(
        nullptr, (const __half*)p_h0, (const __half*)p_h1,
        (const __half*)p_m0, (const __half*)p_m1,
        nullptr, (__half*)p_Q0, (__half*)p_Q1, nullptr, 1.0f,
        512, 512, 512, 512, /*flags*/2,
        0, 0, 0, (long long)512 * 512, 0, (long long)8192 * 512, 0, 0);

    // ---- S = Q' @ h^T   (z = n*128+b)
    k_mma<64, false><<<dim3(2, 1, 1024), 256, SM64C>>>(
        nullptr, (const __half*)p_Q0, (const __half*)p_Q1,
        (const __half*)p_h0, (const __half*)p_h1,
        (float*)p_S, nullptr, nullptr, nullptr, 1.0f,
        512, 512, 512, 256, 0,
        /*aLo*/64 * 512, /*aHi*/(long long)8192 * 512,
        /*bLo*/(long long)256 * 512, /*bHi*/0,
        /*cLo*/64 * 256, /*cHi*/(long long)64 * 256 * 128, /*zmask*/127, /*zshift*/7);

    k_softmax<<<dim3(8192), 256>>>();

    // ---- u planes = prob @ h   (B row-major: h[e,d]), C layout [b,a,n*512+d]
    k_mma<64, true><<<dim3(4, 1, 1024), 256, SM64R>>>(
        nullptr, (const __half*)p_P0, (const __half*)p_P1,
        (const __half*)p_h0, (const __half*)p_h1,
        nullptr, (__half*)p_U0, (__half*)p_U1, nullptr, 1.0f,
        256, 256, 512, 4096, 0,
        /*aLo*/64 * 256, /*aHi*/(long long)64 * 256 * 128,
        /*bLo*/(long long)256 * 512, /*bHi*/0,
        /*cLo*/(long long)64 * 4096, /*cHi*/512, /*zmask*/127, /*zshift*/7);

    // ---- out = (1/8) u @ WVcat
    k_mma<128, false><<<dim3(4, 64, 1), 256, SM128>>>(
        nullptr, (const __half*)p_U0, (const __half*)p_U1,
        (const __half*)p_w0, (const __half*)p_w1,
        out, nullptr, nullptr, nullptr, 0.125f,
        4096, 4096, 4096, 512, 0,
        0, 0, 0, 0, 0, 0, 0, 0);
}

// round 6
// speedup vs baseline: 2.2892x; 1.0506x over previous
#include <cuda_runtime.h>
#include <cuda_fp16.h>
#include <mma.h>
#include <cstdint>
#include <string.h>
#include <math.h>
#include <type_traits>

using namespace nvcuda;

// ===========================================================================
//  h   = lrelu(x) @ W_enc + b            [32768,512]   (WMMA fp16x2-split)
//  M_n = (WQ_n @ WK_n^T) / sqrt(512)     [8,512,512]   (FFMA fp32)
//  Q'  = ha @ M_n                        [8,8192,512]  (WMMA)
//  attn (FUSED): S = Q'@h^T -> softmax -> U = P@h -> U planes [b,a,n*512+d]
//  out = (1/8) u @ WVcat                 [8192,512]    (WMMA)
// All tensor GEMMs: fp16 (hi,lo) split pairs, 3 products
// (a0b0 + a0b1 + a1b0) -> ~22-bit effective precision, fp32 accumulate.
// ===========================================================================

// -------------------- scratch (device globals) -----------------------------
static __device__ float  g_M [8u * 512u * 512u];
static __device__ __half g_h0[32768u * 512u],  g_h1[32768u * 512u];
static __device__ __half g_Q0[8u * 8192u * 512u], g_Q1[8u * 8192u * 512u];
static __device__ __half g_U0[8192u * 4096u], g_U1[8192u * 4096u];
static __device__ __half g_Te0[512u * 256u],  g_Te1[512u * 256u];          // W_enc^T
static __device__ __half g_Tm0[8u * 512u * 512u], g_Tm1[8u * 512u * 512u]; // M^T
static __device__ __half g_Tw0[512u * 4096u], g_Tw1[512u * 4096u];         // WVcat^T

__device__ __forceinline__ float lrelu(float v) { return v > 0.0f ? v : 0.01f * v; }

__device__ __forceinline__ void split2(float v, __half& h0, __half& h1) {
    h0 = __float2half_rn(v);
    h1 = __float2half_rn(v - __half2float(h0));
}

__device__ __forceinline__ uint32_t h2u(__half2 v) {
    uint32_t u;
    memcpy(&u, &v, 4);
    return u;
}

// ---------------------------------------------------------------------------
// tiled transpose + fp16 split2:  T*[n*K+k] = split(B[k*N+n])  (coalesced)
// grid (K/32, N/32, batch), block (32,8)
// ---------------------------------------------------------------------------
__global__ __launch_bounds__(256) void k_tsplit2(const float* __restrict__ B,
                                                 __half* __restrict__ T0,
                                                 __half* __restrict__ T1,
                                                 int K, int N) {
    __shared__ __half s0[32][33];
    __shared__ __half s1[32][33];
    const size_t base = (size_t)blockIdx.z * (size_t)K * N;
    const int k0 = blockIdx.x * 32, n0 = blockIdx.y * 32;
    const int tx = threadIdx.x, ty = threadIdx.y;
#pragma unroll
    for (int i = 0; i < 4; i++) {
        int row = ty * 4 + i;
        float v = B[base + (size_t)(k0 + row) * N + n0 + tx];
        split2(v, s0[row][tx], s1[row][tx]);
    }
    __syncthreads();
#pragma unroll
    for (int i = 0; i < 4; i++) {
        int nrow = ty * 4 + i;
        size_t o = base + (size_t)(n0 + nrow) * K + k0 + tx;
        T0[o] = s0[tx][nrow];
        T1[o] = s1[tx][nrow];
    }
}

// ---------------------------------------------------------------------------
// Generic WMMA GEMM (BM=128, B col-major planes).  See round-5 version.
// ---------------------------------------------------------------------------
template <int BM>
__global__ __launch_bounds__(256) void k_mma(
    const float* __restrict__ Afp,
    const __half* __restrict__ A0g, const __half* __restrict__ A1g,
    const __half* __restrict__ B0g, const __half* __restrict__ B1g,
    float* __restrict__ Cf, __half* __restrict__ C0g, __half* __restrict__ C1g,
    const float* __restrict__ bias, float alpha,
    int Ktot, int lda, int ldb, int ldc,
    int flags,  // 1 = lrelu on fp32 A, 2 = gather rows (b*256+a map)
    long long aHi, long long bHi, long long cHi)
{
    constexpr int WMG = 4;
    constexpr int WN  = 64;
    constexpr int NF  = 4;
    constexpr int LDA = 40;
    constexpr int LDB = 40;
    constexpr int APL = BM * LDA * 2;
    constexpr int BPL = 128 * LDB * 2;
    constexpr int STAGE = 2 * APL + 2 * BPL;
    constexpr int ACH = BM * 4 / 256;
    constexpr int AF4 = BM * 8 / 256;

    extern __shared__ __align__(1024) char sm[];

    const int tid = threadIdx.x;
    const int w = tid >> 5;
    const int wm = w & (WMG - 1);
    const int wn = w / WMG;
    const int zhi = blockIdx.z;
    const long long aoff = (long long)zhi * aHi;
    const long long boff = (long long)zhi * bHi;
    const long long coff = (long long)zhi * cHi;
    const int m0 = blockIdx.y * BM;
    const int n0 = blockIdx.x * 128;
    const bool a_fp32 = (Afp != nullptr);
    const bool gather = (flags & 2) != 0;
    const bool do_lrelu = (flags & 1) != 0;

    int aprow[ACH], apk[ACH];
    int afrow[AF4], afk[AF4];
#pragma unroll
    for (int i = 0; i < ACH; i++) {
        int id = tid + i * 256;
        aprow[i] = id >> 2;
        apk[i] = (id & 3) * 8;
    }
#pragma unroll
    for (int i = 0; i < AF4; i++) {
        int id = tid + i * 256;
        afrow[i] = id >> 3;
        afk[i] = (id & 7) * 4;
    }
    int brow[2], bk[2];
#pragma unroll
    for (int i = 0; i < 2; i++) {
        int id = tid + i * 256;
        brow[i] = id >> 2;
        bk[i] = (id & 3) * 8;
    }

    auto a_grow = [&](int r) -> long long {
        int g = m0 + r;
        return gather ? (long long)(((g >> 6) << 8) + (g & 63)) : (long long)g;
    };

    wmma::fragment<wmma::accumulator, 16, 16, 16, float> acc[2][NF];
#pragma unroll
    for (int mf = 0; mf < 2; mf++)
#pragma unroll
        for (int nf = 0; nf < NF; nf++) wmma::fill_fragment(acc[mf][nf], 0.0f);

    uint4 ra0[ACH], ra1[ACH];
    float4 rf[AF4];
    uint4 rb0[2], rb1[2];

    auto load_tile = [&](int k0) {
        if (a_fp32) {
#pragma unroll
            for (int i = 0; i < AF4; i++)
                rf[i] = *(const float4*)(Afp + aoff + a_grow(afrow[i]) * lda + k0 + afk[i]);
        } else {
#pragma unroll
            for (int i = 0; i < ACH; i++) {
                long long r = aoff + a_grow(aprow[i]) * lda + k0 + apk[i];
                ra0[i] = *(const uint4*)(A0g + r);
                ra1[i] = *(const uint4*)(A1g + r);
            }
        }
#pragma unroll
        for (int i = 0; i < 2; i++) {
            long long r = boff + (long long)(n0 + brow[i]) * ldb + k0 + bk[i];
            rb0[i] = *(const uint4*)(B0g + r);
            rb1[i] = *(const uint4*)(B1g + r);
        }
    };

    auto store_tile = [&](int buf) {
        char* base = sm + buf * STAGE;
        char* sA0 = base;
        char* sA1 = base + APL;
        char* sB0 = base + 2 * APL;
        char* sB1 = base + 2 * APL + BPL;
        if (a_fp32) {
#pragma unroll
            for (int i = 0; i < AF4; i++) {
                float4 v = rf[i];
                if (do_lrelu) { v.x = lrelu(v.x); v.y = lrelu(v.y); v.z = lrelu(v.z); v.w = lrelu(v.w); }
                __half x0, x1, y0, y1, z0, z1, w0, w1;
                split2(v.x, x0, x1); split2(v.y, y0, y1);
                split2(v.z, z0, z1); split2(v.w, w0, w1);
                int off = afrow[i] * (LDA * 2) + afk[i] * 2;
                __half2 p0 = __halves2half2(x0, y0), q0 = __halves2half2(z0, w0);
                __half2 p1 = __halves2half2(x1, y1), q1 = __halves2half2(z1, w1);
                *(uint2*)(sA0 + off) = make_uint2(h2u(p0), h2u(q0));
                *(uint2*)(sA1 + off) = make_uint2(h2u(p1), h2u(q1));
            }
        } else {
#pragma unroll
            for (int i = 0; i < ACH; i++) {
                int off = aprow[i] * (LDA * 2) + apk[i] * 2;
                *(uint4*)(sA0 + off) = ra0[i];
                *(uint4*)(sA1 + off) = ra1[i];
            }
        }
#pragma unroll
        for (int i = 0; i < 2; i++) {
            int off = brow[i] * (LDB * 2) + bk[i] * 2;
            *(uint4*)(sB0 + off) = rb0[i];
            *(uint4*)(sB1 + off) = rb1[i];
        }
    };

    auto mma_tile = [&](int buf) {
        const char* base = sm + buf * STAGE;
        const __half* sA0 = (const __half*)(base);
        const __half* sA1 = (const __half*)(base + APL);
        const __half* sB0 = (const __half*)(base + 2 * APL);
        const __half* sB1 = (const __half*)(base + 2 * APL + BPL);
#pragma unroll
        for (int ks = 0; ks < 32; ks += 16) {
            wmma::fragment<wmma::matrix_a, 16, 16, 16, __half, wmma::row_major> a0f[2], a1f[2];
#pragma unroll
            for (int mf = 0; mf < 2; mf++) {
                int r0 = wm * 32 + mf * 16;
                wmma::load_matrix_sync(a0f[mf], sA0 + r0 * LDA + ks, LDA);
                wmma::load_matrix_sync(a1f[mf], sA1 + r0 * LDA + ks, LDA);
            }
#pragma unroll
            for (int nf = 0; nf < NF; nf++) {
                int col = wn * WN + nf * 16;
                wmma::fragment<wmma::matrix_b, 16, 16, 16, __half, wmma::col_major> b0f, b1f;
                wmma::load_matrix_sync(b0f, sB0 + col * LDB + ks, LDB);
                wmma::load_matrix_sync(b1f, sB1 + col * LDB + ks, LDB);
#pragma unroll
                for (int mf = 0; mf < 2; mf++) {
                    wmma::mma_sync(acc[mf][nf], a0f[mf], b0f, acc[mf][nf]);
                    wmma::mma_sync(acc[mf][nf], a0f[mf], b1f, acc[mf][nf]);
                    wmma::mma_sync(acc[mf][nf], a1f[mf], b0f, acc[mf][nf]);
                }
            }
        }
    };

    const int numK = Ktot >> 5;
    load_tile(0);
    for (int t = 0; t < numK; t++) {
        store_tile(t & 1);
        __syncthreads();
        if (t + 1 < numK) load_tile((t + 1) << 5);
        mma_tile(t & 1);
    }

    __syncthreads();
    float* Csm = (float*)sm;
#pragma unroll
    for (int mf = 0; mf < 2; mf++)
#pragma unroll
        for (int nf = 0; nf < NF; nf++) {
            int r0 = wm * 32 + mf * 16, c0 = wn * WN + nf * 16;
            wmma::store_matrix_sync(Csm + r0 * 128 + c0, acc[mf][nf], 128, wmma::mem_row_major);
        }
    __syncthreads();

    const int NOUT = BM * 128 / 4 / 256;
#pragma unroll
    for (int i = 0; i < NOUT; i++) {
        int f = tid + i * 256;
        int row = f >> 5, c4 = (f & 31) * 4;
        float4 v = *(float4*)(Csm + row * 128 + c4);
        v.x *= alpha; v.y *= alpha; v.z *= alpha; v.w *= alpha;
        if (bias) {
            v.x += bias[n0 + c4 + 0]; v.y += bias[n0 + c4 + 1];
            v.z += bias[n0 + c4 + 2]; v.w += bias[n0 + c4 + 3];
        }
        long long o = coff + (long long)(m0 + row) * ldc + n0 + c4;
        if (Cf) {
            *(float4*)(Cf + o) = v;
        } else {
            __half x0, x1, y0, y1, z0, z1, w0, w1;
            split2(v.x, x0, x1); split2(v.y, y0, y1);
            split2(v.z, z0, z1); split2(v.w, w0, w1);
            __half2 p0 = __halves2half2(x0, y0), q0 = __halves2half2(z0, w0);
            __half2 p1 = __halves2half2(x1, y1), q1 = __halves2half2(z1, w1);
            *(uint2*)(C0g + o) = make_uint2(h2u(p0), h2u(q0));
            *(uint2*)(C1g + o) = make_uint2(h2u(p1), h2u(q1));
        }
    }
}

// ---------------------------------------------------------------------------
// Fused attention: per (b, n) CTA:
//   S[64,256] = Q'[64,512] @ h_b^T      (WMMA 3-term)
//   P = softmax(S)  (fp32 in smem, split planes to smem)
//   U[64,512] = P @ h_b                 (WMMA 3-term, two 256-col halves)
//   write U planes to g_U layout [b,a,n*512+d]
// smem layout (total 135168):
//   phase1 stage: 2 x 51200 @ 0
//   S fp32:       64x264x4 = 67584 @ 0        (after phase1)
//   P planes:     2 x 64x264x2 = 67584 @ 67584
//   phase3 stage: 2 x 33792 @ 0               (after softmax)
//   C fp32:       67584 @ 0                   (after phase3 K loop)
// ---------------------------------------------------------------------------
#define ATTN_SMEM 135168

__global__ __launch_bounds__(256) void k_attn() {
    extern __shared__ __align__(1024) char sm[];
    const int tid = threadIdx.x;
    const int w = tid >> 5, lane = tid & 31;
    const int wm = w & 1, wn = w >> 1;     // 2 x 4 warp grid, warp tile 32x64
    const int b = blockIdx.x, n = blockIdx.y;

    float* Ssm = (float*)sm;                               // 64 x 264 fp32
    __half* Psm0 = (__half*)(sm + 67584);                  // 64 x 264
    __half* Psm1 = (__half*)(sm + 67584 + 33792);

    const __half* Qb0 = g_Q0 + ((size_t)n * 8192 + (size_t)b * 64) * 512;
    const __half* Qb1 = g_Q1 + ((size_t)n * 8192 + (size_t)b * 64) * 512;
    const __half* Hb0 = g_h0 + (size_t)b * 256 * 512;
    const __half* Hb1 = g_h1 + (size_t)b * 256 * 512;

    wmma::fragment<wmma::accumulator, 16, 16, 16, float> acc[2][4];
#pragma unroll
    for (int mf = 0; mf < 2; mf++)
#pragma unroll
        for (int nf = 0; nf < 4; nf++) wmma::fill_fragment(acc[mf][nf], 0.0f);

    // ======== phase 1: S = Q' @ h^T  (K=512, 16 chunks of 32) ========
    {
        const int arow = tid >> 2, akc = (tid & 3) * 8;
        uint4 ra0, ra1, rb0[4], rb1[4];
        auto p1_load = [&](int k0) {
            ra0 = *(const uint4*)(Qb0 + (size_t)arow * 512 + k0 + akc);
            ra1 = *(const uint4*)(Qb1 + (size_t)arow * 512 + k0 + akc);
#pragma unroll
            for (int i = 0; i < 4; i++) {
                int id = tid + i * 256;
                int br = id >> 2, bkc = (id & 3) * 8;
                rb0[i] = *(const uint4*)(Hb0 + (size_t)br * 512 + k0 + bkc);
                rb1[i] = *(const uint4*)(Hb1 + (size_t)br * 512 + k0 + bkc);
            }
        };
        auto p1_store = [&](int buf) {
            char* base = sm + buf * 51200;
            __half* sA0 = (__half*)base;
            __half* sA1 = (__half*)(base + 5120);
            __half* sB0 = (__half*)(base + 10240);
            __half* sB1 = (__half*)(base + 30720);
            *(uint4*)(sA0 + arow * 40 + akc) = ra0;
            *(uint4*)(sA1 + arow * 40 + akc) = ra1;
#pragma unroll
            for (int i = 0; i < 4; i++) {
                int id = tid + i * 256;
                int br = id >> 2, bkc = (id & 3) * 8;
                *(uint4*)(sB0 + br * 40 + bkc) = rb0[i];
                *(uint4*)(sB1 + br * 40 + bkc) = rb1[i];
            }
        };
        auto p1_mma = [&](int buf) {
            const char* base = sm + buf * 51200;
            const __half* sA0 = (const __half*)base;
            const __half* sA1 = (const __half*)(base + 5120);
            const __half* sB0 = (const __half*)(base + 10240);
            const __half* sB1 = (const __half*)(base + 30720);
#pragma unroll
            for (int ks = 0; ks < 32; ks += 16) {
                wmma::fragment<wmma::matrix_a, 16, 16, 16, __half, wmma::row_major> a0f[2], a1f[2];
#pragma unroll
                for (int mf = 0; mf < 2; mf++) {
                    int r0 = wm * 32 + mf * 16;
                    wmma::load_matrix_sync(a0f[mf], sA0 + r0 * 40 + ks, 40);
                    wmma::load_matrix_sync(a1f[mf], sA1 + r0 * 40 + ks, 40);
                }
#pragma unroll
                for (int nf = 0; nf < 4; nf++) {
                    int col = wn * 64 + nf * 16;
                    wmma::fragment<wmma::matrix_b, 16, 16, 16, __half, wmma::col_major> b0f, b1f;
                    wmma::load_matrix_sync(b0f, sB0 + col * 40 + ks, 40);
                    wmma::load_matrix_sync(b1f, sB1 + col * 40 + ks, 40);
#pragma unroll
                    for (int mf = 0; mf < 2; mf++) {
                        wmma::mma_sync(acc[mf][nf], a0f[mf], b0f, acc[mf][nf]);
                        wmma::mma_sync(acc[mf][nf], a0f[mf], b1f, acc[mf][nf]);
                        wmma::mma_sync(acc[mf][nf], a1f[mf], b0f, acc[mf][nf]);
                    }
                }
            }
        };
        p1_load(0);
        for (int t = 0; t < 16; t++) {
            p1_store(t & 1);
            __syncthreads();
            if (t + 1 < 16) p1_load((t + 1) << 5);
            p1_mma(t & 1);
        }
    }

    // ======== stage S -> smem fp32 ========
    __syncthreads();
#pragma unroll
    for (int mf = 0; mf < 2; mf++)
#pragma unroll
        for (int nf = 0; nf < 4; nf++) {
            int r0 = wm * 32 + mf * 16, c0 = wn * 64 + nf * 16;
            wmma::store_matrix_sync(Ssm + r0 * 264 + c0, acc[mf][nf], 264, wmma::mem_row_major);
        }
    __syncthreads();

    // ======== softmax: warp w owns rows w*8 .. w*8+7 ========
#pragma unroll
    for (int i = 0; i < 8; i++) {
        int r = w * 8 + i;
        float* srow = Ssm + (size_t)r * 264 + lane * 8;
        float4 v0 = *(float4*)srow;
        float4 v1 = *(float4*)(srow + 4);
        float m = fmaxf(fmaxf(fmaxf(v0.x, v0.y), fmaxf(v0.z, v0.w)),
                        fmaxf(fmaxf(v1.x, v1.y), fmaxf(v1.z, v1.w)));
#pragma unroll
        for (int off = 16; off > 0; off >>= 1)
            m = fmaxf(m, __shfl_xor_sync(0xffffffffu, m, off));
        v0.x = __expf(v0.x - m); v0.y = __expf(v0.y - m);
        v0.z = __expf(v0.z - m); v0.w = __expf(v0.w - m);
        v1.x = __expf(v1.x - m); v1.y = __expf(v1.y - m);
        v1.z = __expf(v1.z - m); v1.w = __expf(v1.w - m);
        float s = v0.x + v0.y + v0.z + v0.w + v1.x + v1.y + v1.z + v1.w;
#pragma unroll
        for (int off = 16; off > 0; off >>= 1)
            s += __shfl_xor_sync(0xffffffffu, s, off);
        const float inv = 1.0f / s;
        float p[8] = {v0.x * inv, v0.y * inv, v0.z * inv, v0.w * inv,
                      v1.x * inv, v1.y * inv, v1.z * inv, v1.w * inv};
        __align__(16) __half h0[8];
        __align__(16) __half h1[8];
#pragma unroll
        for (int j = 0; j < 8; j++) split2(p[j], h0[j], h1[j]);
        *(uint4*)(Psm0 + (size_t)r * 264 + lane * 8) = *(uint4*)h0;
        *(uint4*)(Psm1 + (size_t)r * 264 + lane * 8) = *(uint4*)h1;
    }
    __syncthreads();

    // ======== phase 3: U = P @ h  (two 256-col halves; K=256, 8 chunks) ===
    for (int hh = 0; hh < 2; hh++) {
        const int d0 = hh * 256;
#pragma unroll
        for (int mf = 0; mf < 2; mf++)
#pragma unroll
            for (int nf = 0; nf < 4; nf++) wmma::fill_fragment(acc[mf][nf], 0.0f);

        uint4 rh0[4], rh1[4];
        auto p3_load = [&](int k0) {
#pragma unroll
            for (int i = 0; i < 4; i++) {
                int id = tid + i * 256;
                int er = id >> 5, dc = id & 31;
                rh0[i] = *(const uint4*)(Hb0 + (size_t)(k0 + er) * 512 + d0 + dc * 8);
                rh1[i] = *(const uint4*)(Hb1 + (size_t)(k0 + er) * 512 + d0 + dc * 8);
            }
        };
        auto p3_store = [&](int buf) {
            __half* sH0 = (__half*)(sm + buf * 33792);
            __half* sH1 = (__half*)(sm + buf * 33792 + 16896);
#pragma unroll
            for (int i = 0; i < 4; i++) {
                int id = tid + i * 256;
                int er = id >> 5, dc = id & 31;
                *(uint4*)(sH0 + er * 264 + dc * 8) = rh0[i];
                *(uint4*)(sH1 + er * 264 + dc * 8) = rh1[i];
            }
        };
        auto p3_mma = [&](int buf, int c) {
            const __half* sH0 = (const __half*)(sm + buf * 33792);
            const __half* sH1 = (const __half*)(sm + buf * 33792 + 16896);
#pragma unroll
            for (int ks = 0; ks < 32; ks += 16) {
                wmma::fragment<wmma::matrix_a, 16, 16, 16, __half, wmma::row_major> a0f[2], a1f[2];
#pragma unroll
                for (int mf = 0; mf < 2; mf++) {
                    int r0 = wm * 32 + mf * 16;
                    wmma::load_matrix_sync(a0f[mf], Psm0 + r0 * 264 + c * 32 + ks, 264);
                    wmma::load_matrix_sync(a1f[mf], Psm1 + r0 * 264 + c * 32 + ks, 264);
                }
#pragma unroll
                for (int nf = 0; nf < 4; nf++) {
                    int col = wn * 64 + nf * 16;
                    wmma::fragment<wmma::matrix_b, 16, 16, 16, __half, wmma::row_major> b0f, b1f;
                    wmma::load_matrix_sync(b0f, sH0 + ks * 264 + col, 264);
                    wmma::load_matrix_sync(b1f, sH1 + ks * 264 + col, 264);
#pragma unroll
                    for (int mf = 0; mf < 2; mf++) {
                        wmma::mma_sync(acc[mf][nf], a0f[mf], b0f, acc[mf][nf]);
                        wmma::mma_sync(acc[mf][nf], a0f[mf], b1f, acc[mf][nf]);
                        wmma::mma_sync(acc[mf][nf], a1f[mf], b0f, acc[mf][nf]);
                    }
                }
            }
        };
        p3_load(0);
        for (int c = 0; c < 8; c++) {
            p3_store(c & 1);
            __syncthreads();
            if (c + 1 < 8) p3_load((c + 1) << 5);
            p3_mma(c & 1, c);
        }

        // epilogue for this half
        __syncthreads();
        float* Csm = (float*)sm;
#pragma unroll
        for (int mf = 0; mf < 2; mf++)
#pragma unroll
            for (int nf = 0; nf < 4; nf++) {
                int r0 = wm * 32 + mf * 16, c0 = wn * 64 + nf * 16;
                wmma::store_matrix_sync(Csm + r0 * 264 + c0, acc[mf][nf], 264, wmma::mem_row_major);
            }
        __syncthreads();
#pragma unroll
        for (int i = 0; i < 16; i++) {
            int id = tid + i * 256;
            int row = id >> 6, c4 = (id & 63) * 4;
            float4 v = *(float4*)(Csm + row * 264 + c4);
            __half x0, x1, y0, y1, z0, z1, w0, w1;
            split2(v.x, x0, x1); split2(v.y, y0, y1);
            split2(v.z, z0, z1); split2(v.w, w0, w1);
            __half2 p0 = __halves2half2(x0, y0), q0 = __halves2half2(z0, w0);
            __half2 p1 = __halves2half2(x1, y1), q1 = __halves2half2(z1, w1);
            size_t o = (((size_t)(b * 64 + row)) * 8 + n) * 512 + d0 + c4;
            *(uint2*)(g_U0 + o) = make_uint2(h2u(p0), h2u(q0));
            *(uint2*)(g_U1 + o) = make_uint2(h2u(p1), h2u(q1));
        }
        __syncthreads();
    }
}

// ---------------------------------------------------------------------------
// M_n = (WQ_n @ WK_n^T) * scale   (FFMA fp32, small)
// ---------------------------------------------------------------------------
__global__ __launch_bounds__(256) void k_wqwk(const float* __restrict__ WQ,
                                              const float* __restrict__ WK) {
    __shared__ float As[8][128];
    __shared__ float Bs[8][128];
    const int n = blockIdx.z;
    const int tid = threadIdx.x;
    const int bn = blockIdx.x, bm = blockIdx.y;
    const int ty = tid >> 4, tx = tid & 15;
    const int arow = tid >> 1, acol = (tid & 1) * 4;

    const float* Ap = WQ + (size_t)n * 512 * 512 + (size_t)(bm * 128 + arow) * 512 + acol;
    const float* Bp = WK + (size_t)n * 512 * 512 + (size_t)(bn * 128 + arow) * 512 + acol;

    float acc[8][8];
#pragma unroll
    for (int i = 0; i < 8; i++)
#pragma unroll
        for (int j = 0; j < 8; j++) acc[i][j] = 0.0f;

    float4 a_n = *(const float4*)Ap;
    float4 b_n = *(const float4*)Bp;

    for (int ko = 0; ko < 512; ko += 8) {
        As[acol + 0][arow] = a_n.x; As[acol + 1][arow] = a_n.y;
        As[acol + 2][arow] = a_n.z; As[acol + 3][arow] = a_n.w;
        Bs[acol + 0][arow] = b_n.x; Bs[acol + 1][arow] = b_n.y;
        Bs[acol + 2][arow] = b_n.z; Bs[acol + 3][arow] = b_n.w;
        __syncthreads();
        if (ko + 8 < 512) {
            a_n = *(const float4*)(Ap + ko + 8);
            b_n = *(const float4*)(Bp + ko + 8);
        }
#pragma unroll
        for (int kk = 0; kk < 8; kk++) {
            float a[8], b[8];
#pragma unroll
            for (int i = 0; i < 8; i++) a[i] = As[kk][ty * 8 + i];
#pragma unroll
            for (int j = 0; j < 8; j++) b[j] = Bs[kk][tx * 8 + j];
#pragma unroll
            for (int i = 0; i < 8; i++)
#pragma unroll
                for (int j = 0; j < 8; j++) acc[i][j] += a[i] * b[j];
        }
        __syncthreads();
    }
    const float scale = 0.04419417382415922f;
    float* Cm = g_M + (size_t)n * 512 * 512;
    const int row0 = bm * 128 + ty * 8;
    const int col0 = bn * 128 + tx * 8;
#pragma unroll
    for (int i = 0; i < 8; i++) {
        float4 o0 = make_float4(acc[i][0] * scale, acc[i][1] * scale, acc[i][2] * scale, acc[i][3] * scale);
        float4 o1 = make_float4(acc[i][4] * scale, acc[i][5] * scale, acc[i][6] * scale, acc[i][7] * scale);
        float* dst = Cm + (size_t)(row0 + i) * 512 + col0;
        *(float4*)dst = o0;
        *(float4*)(dst + 4) = o1;
    }
}

// ---------------------------------------------------------------------------
extern "C" void kernel_launch(void* const* d_in, const int* in_sizes, int n_in,
                              void* d_out, int out_size) {
    const float* x     = (const float*)d_in[0];
    const float* W_enc = (const float*)d_in[1];
    const float* b_enc = (const float*)d_in[2];
    const float* WQ    = (const float*)d_in[3];
    const float* WK    = (const float*)d_in[4];
    const float* WV    = (const float*)d_in[5];
    float* out = (float*)d_out;

    const int SM128 = 2 * (2 * 128 * 40 * 2 + 2 * 128 * 40 * 2);   // 81920
    cudaFuncSetAttribute(k_mma<128>, cudaFuncAttributeMaxDynamicSharedMemorySize, SM128);
    cudaFuncSetAttribute(k_attn, cudaFuncAttributeMaxDynamicSharedMemorySize, ATTN_SMEM);

    void *p_M, *p_h0, *p_h1, *p_Q0, *p_Q1, *p_U0, *p_U1;
    void *p_e0, *p_e1, *p_m0, *p_m1, *p_w0, *p_w1;
    cudaGetSymbolAddress(&p_M, g_M);
    cudaGetSymbolAddress(&p_h0, g_h0); cudaGetSymbolAddress(&p_h1, g_h1);
    cudaGetSymbolAddress(&p_Q0, g_Q0); cudaGetSymbolAddress(&p_Q1, g_Q1);
    cudaGetSymbolAddress(&p_U0, g_U0); cudaGetSymbolAddress(&p_U1, g_U1);
    cudaGetSymbolAddress(&p_e0, g_Te0); cudaGetSymbolAddress(&p_e1, g_Te1);
    cudaGetSymbolAddress(&p_m0, g_Tm0); cudaGetSymbolAddress(&p_m1, g_Tm1);
    cudaGetSymbolAddress(&p_w0, g_Tw0); cudaGetSymbolAddress(&p_w1, g_Tw1);

    // ---- weight prep (tiled transpose+split)
    k_tsplit2<<<dim3(8, 16, 1), dim3(32, 8)>>>(W_enc, (__half*)p_e0, (__half*)p_e1, 256, 512);
    k_tsplit2<<<dim3(128, 16, 1), dim3(32, 8)>>>(WV, (__half*)p_w0, (__half*)p_w1, 4096, 512);
    k_wqwk<<<dim3(4, 4, 8), 256>>>(WQ, WK);
    k_tsplit2<<<dim3(16, 16, 8), dim3(32, 8)>>>((const float*)p_M, (__half*)p_m0, (__half*)p_m1, 512, 512);

    // ---- encode: h planes = lrelu(x) @ W_enc + b
    k_mma<128><<<dim3(4, 256, 1), 256, SM128>>>(
        x, nullptr, nullptr, (const __half*)p_e0, (const __half*)p_e1,
        nullptr, (__half*)p_h0, (__half*)p_h1, b_enc, 1.0f,
        256, 256, 256, 512, /*flags*/1, 0, 0, 0);

    // ---- Q' planes = ha @ M_n   (gather, batched over heads)
    k_mma<128><<<dim3(4, 64, 8), 256, SM128>>>(
        nullptr, (const __half*)p_h0, (const __half*)p_h1,
        (const __half*)p_m0, (const __half*)p_m1,
        nullptr, (__half*)p_Q0, (__half*)p_Q1, nullptr, 1.0f,
        512, 512, 512, 512, /*flags*/2,
        0, (long long)512 * 512, (long long)8192 * 512);

    // ---- fused attention
    k_attn<<<dim3(128, 8), 256, ATTN_SMEM>>>();

    // ---- out = (1/8) u @ WVcat
    k_mma<128><<<dim3(4, 64, 1), 256, SM128>>>(
        nullptr, (const __half*)p_U0, (const __half*)p_U1,
        (const __half*)p_w0, (const __half*)p_w1,
        out, nullptr, nullptr, nullptr, 0.125f,
        4096, 4096, 4096, 512, 0, 0, 0, 0);
}

// round 8
// speedup vs baseline: 3.1003x; 1.3543x over previous
#include <cuda_runtime.h>
#include <cuda_fp16.h>
#include <mma.h>
#include <cstdint>
#include <string.h>
#include <math.h>
#include <type_traits>

using namespace nvcuda;

// ===========================================================================
//  h   = lrelu(x) @ W_enc + b         [32768,512]  WMMA 3-term split
//  M_n = (WQ_n @ WK_n^T)/sqrt(512)    [8,512,512]  WMMA 3-term (WK no transp)
//  Q'  = ha @ M_n                     [8,8192,512] WMMA 3-term
//  attn fused: S=Q'@h^T (3-term) -> softmax -> U=P@h (1-term fp16)
//  out = (1/8) U @ WVcat              [8192,512]   WMMA 1-term fp16
// Score path keeps ~22-bit precision; post-softmax path is linear and
// tolerates plain fp16 (~2e-4 rel), cutting MMA products 335->232 GF.
// ===========================================================================

// -------------------- scratch (device globals) -----------------------------
static __device__ float  g_M [8u * 512u * 512u];
static __device__ __half g_h0[32768u * 512u],  g_h1[32768u * 512u];
static __device__ __half g_Q0[8u * 8192u * 512u], g_Q1[8u * 8192u * 512u];
static __device__ __half g_U0[8192u * 4096u];                              // 1-term
static __device__ __half g_Te0[512u * 256u],  g_Te1[512u * 256u];          // W_enc^T
static __device__ __half g_Tm0[8u * 512u * 512u], g_Tm1[8u * 512u * 512u]; // M^T
static __device__ __half g_Tw0[512u * 4096u], g_Tw1[512u * 4096u];         // WVcat^T
static __device__ __half g_Wk0[8u * 512u * 512u], g_Wk1[8u * 512u * 512u]; // WK split

__device__ __forceinline__ float lrelu(float v) { return v > 0.0f ? v : 0.01f * v; }

__device__ __forceinline__ void split2(float v, __half& h0, __half& h1) {
    h0 = __float2half_rn(v);
    h1 = __float2half_rn(v - __half2float(h0));
}

__device__ __forceinline__ uint32_t h2u(__half2 v) {
    uint32_t u;
    memcpy(&u, &v, 4);
    return u;
}

// ---------------------------------------------------------------------------
// elementwise fp16 split2 (no transpose)
// ---------------------------------------------------------------------------
__global__ __launch_bounds__(256) void k_split2e(const float* __restrict__ B,
                                                 __half* __restrict__ T0,
                                                 __half* __restrict__ T1,
                                                 size_t total) {
    for (size_t i = (size_t)blockIdx.x * 256 + threadIdx.x; i < total;
         i += (size_t)gridDim.x * 256) {
        split2(B[i], T0[i], T1[i]);
    }
}

// ---------------------------------------------------------------------------
// tiled transpose + fp16 split2:  T*[n*K+k] = split(B[k*N+n])  (coalesced)
// grid (K/32, N/32, batch), block (32,8)
// ---------------------------------------------------------------------------
__global__ __launch_bounds__(256) void k_tsplit2(const float* __restrict__ B,
                                                 __half* __restrict__ T0,
                                                 __half* __restrict__ T1,
                                                 int K, int N) {
    __shared__ __half s0[32][33];
    __shared__ __half s1[32][33];
    const size_t base = (size_t)blockIdx.z * (size_t)K * N;
    const int k0 = blockIdx.x * 32, n0 = blockIdx.y * 32;
    const int tx = threadIdx.x, ty = threadIdx.y;
#pragma unroll
    for (int i = 0; i < 4; i++) {
        int row = ty * 4 + i;
        float v = B[base + (size_t)(k0 + row) * N + n0 + tx];
        split2(v, s0[row][tx], s1[row][tx]);
    }
    __syncthreads();
#pragma unroll
    for (int i = 0; i < 4; i++) {
        int nrow = ty * 4 + i;
        size_t o = base + (size_t)(n0 + nrow) * K + k0 + tx;
        T0[o] = s0[tx][nrow];
        T1[o] = s1[tx][nrow];
    }
}

// ---------------------------------------------------------------------------
// Generic WMMA GEMM (BM=128 rows, 128 cols).  NT=3: split-pair 3-product.
// NT=1: plain fp16 single product (plane 0 only).
// NOTE: epilogue stages C as fp32 through smem: needs >= BM*128*4 bytes of
// dynamic smem regardless of NT (the NT=1 stage alone is smaller than that).
// ---------------------------------------------------------------------------
template <int BM, int NT>
__global__ __launch_bounds__(256) void k_mma(
    const float* __restrict__ Afp,
    const __half* __restrict__ A0g, const __half* __restrict__ A1g,
    const __half* __restrict__ B0g, const __half* __restrict__ B1g,
    float* __restrict__ Cf, __half* __restrict__ C0g, __half* __restrict__ C1g,
    const float* __restrict__ bias, float alpha,
    int Ktot, int lda, int ldb, int ldc,
    int flags,  // 1 = lrelu on fp32 A, 2 = gather rows (b*256+a map)
    long long aHi, long long bHi, long long cHi)
{
    constexpr int WMG = 4;
    constexpr int WN  = 64;
    constexpr int NF  = 4;
    constexpr int LDA = 40;
    constexpr int LDB = 40;
    constexpr int PL  = (NT > 1) ? 2 : 1;
    constexpr int APL = BM * LDA * 2;
    constexpr int BPL = 128 * LDB * 2;
    constexpr int STAGE = PL * (APL + BPL);
    constexpr int ACH = BM * 4 / 256;
    constexpr int AF4 = BM * 8 / 256;

    extern __shared__ __align__(1024) char sm[];

    const int tid = threadIdx.x;
    const int w = tid >> 5;
    const int wm = w & (WMG - 1);
    const int wn = w / WMG;
    const long long aoff = (long long)blockIdx.z * aHi;
    const long long boff = (long long)blockIdx.z * bHi;
    const long long coff = (long long)blockIdx.z * cHi;
    const int m0 = blockIdx.y * BM;
    const int n0 = blockIdx.x * 128;
    const bool a_fp32 = (Afp != nullptr);
    const bool gather = (flags & 2) != 0;
    const bool do_lrelu = (flags & 1) != 0;

    int aprow[ACH], apk[ACH];
    int afrow[AF4], afk[AF4];
#pragma unroll
    for (int i = 0; i < ACH; i++) {
        int id = tid + i * 256;
        aprow[i] = id >> 2;
        apk[i] = (id & 3) * 8;
    }
#pragma unroll
    for (int i = 0; i < AF4; i++) {
        int id = tid + i * 256;
        afrow[i] = id >> 3;
        afk[i] = (id & 7) * 4;
    }
    int brow[2], bk[2];
#pragma unroll
    for (int i = 0; i < 2; i++) {
        int id = tid + i * 256;
        brow[i] = id >> 2;
        bk[i] = (id & 3) * 8;
    }

    auto a_grow = [&](int r) -> long long {
        int g = m0 + r;
        return gather ? (long long)(((g >> 6) << 8) + (g & 63)) : (long long)g;
    };

    wmma::fragment<wmma::accumulator, 16, 16, 16, float> acc[2][NF];
#pragma unroll
    for (int mf = 0; mf < 2; mf++)
#pragma unroll
        for (int nf = 0; nf < NF; nf++) wmma::fill_fragment(acc[mf][nf], 0.0f);

    uint4 ra0[ACH], ra1[ACH];
    float4 rf[AF4];
    uint4 rb0[2], rb1[2];

    auto load_tile = [&](int k0) {
        if (a_fp32) {
#pragma unroll
            for (int i = 0; i < AF4; i++)
                rf[i] = *(const float4*)(Afp + aoff + a_grow(afrow[i]) * lda + k0 + afk[i]);
        } else {
#pragma unroll
            for (int i = 0; i < ACH; i++) {
                long long r = aoff + a_grow(aprow[i]) * lda + k0 + apk[i];
                ra0[i] = *(const uint4*)(A0g + r);
                if (NT > 1) ra1[i] = *(const uint4*)(A1g + r);
            }
        }
#pragma unroll
        for (int i = 0; i < 2; i++) {
            long long r = boff + (long long)(n0 + brow[i]) * ldb + k0 + bk[i];
            rb0[i] = *(const uint4*)(B0g + r);
            if (NT > 1) rb1[i] = *(const uint4*)(B1g + r);
        }
    };

    auto store_tile = [&](int buf) {
        char* base = sm + buf * STAGE;
        char* sA0 = base;
        char* sA1 = base + APL;
        char* sB0 = base + PL * APL;
        char* sB1 = base + PL * APL + BPL;
        if (a_fp32) {
#pragma unroll
            for (int i = 0; i < AF4; i++) {
                float4 v = rf[i];
                if (do_lrelu) { v.x = lrelu(v.x); v.y = lrelu(v.y); v.z = lrelu(v.z); v.w = lrelu(v.w); }
                __half x0, x1, y0, y1, z0, z1, w0, w1;
                split2(v.x, x0, x1); split2(v.y, y0, y1);
                split2(v.z, z0, z1); split2(v.w, w0, w1);
                int off = afrow[i] * (LDA * 2) + afk[i] * 2;
                __half2 p0 = __halves2half2(x0, y0), q0 = __halves2half2(z0, w0);
                *(uint2*)(sA0 + off) = make_uint2(h2u(p0), h2u(q0));
                if (NT > 1) {
                    __half2 p1 = __halves2half2(x1, y1), q1 = __halves2half2(z1, w1);
                    *(uint2*)(sA1 + off) = make_uint2(h2u(p1), h2u(q1));
                }
            }
        } else {
#pragma unroll
            for (int i = 0; i < ACH; i++) {
                int off = aprow[i] * (LDA * 2) + apk[i] * 2;
                *(uint4*)(sA0 + off) = ra0[i];
                if (NT > 1) *(uint4*)(sA1 + off) = ra1[i];
            }
        }
#pragma unroll
        for (int i = 0; i < 2; i++) {
            int off = brow[i] * (LDB * 2) + bk[i] * 2;
            *(uint4*)(sB0 + off) = rb0[i];
            if (NT > 1) *(uint4*)(sB1 + off) = rb1[i];
        }
    };

    auto mma_tile = [&](int buf) {
        const char* base = sm + buf * STAGE;
        const __half* sA0 = (const __half*)(base);
        const __half* sA1 = (const __half*)(base + APL);
        const __half* sB0 = (const __half*)(base + PL * APL);
        const __half* sB1 = (const __half*)(base + PL * APL + BPL);
#pragma unroll
        for (int ks = 0; ks < 32; ks += 16) {
            wmma::fragment<wmma::matrix_a, 16, 16, 16, __half, wmma::row_major> a0f[2], a1f[2];
#pragma unroll
            for (int mf = 0; mf < 2; mf++) {
                int r0 = wm * 32 + mf * 16;
                wmma::load_matrix_sync(a0f[mf], sA0 + r0 * LDA + ks, LDA);
                if (NT > 1) wmma::load_matrix_sync(a1f[mf], sA1 + r0 * LDA + ks, LDA);
            }
#pragma unroll
            for (int nf = 0; nf < NF; nf++) {
                int col = wn * WN + nf * 16;
                wmma::fragment<wmma::matrix_b, 16, 16, 16, __half, wmma::col_major> b0f, b1f;
                wmma::load_matrix_sync(b0f, sB0 + col * LDB + ks, LDB);
                if (NT > 1) wmma::load_matrix_sync(b1f, sB1 + col * LDB + ks, LDB);
#pragma unroll
                for (int mf = 0; mf < 2; mf++) {
                    wmma::mma_sync(acc[mf][nf], a0f[mf], b0f, acc[mf][nf]);
                    if (NT > 1) {
                        wmma::mma_sync(acc[mf][nf], a0f[mf], b1f, acc[mf][nf]);
                        wmma::mma_sync(acc[mf][nf], a1f[mf], b0f, acc[mf][nf]);
                    }
                }
            }
        }
    };

    const int numK = Ktot >> 5;
    load_tile(0);
    for (int t = 0; t < numK; t++) {
        store_tile(t & 1);
        __syncthreads();
        if (t + 1 < numK) load_tile((t + 1) << 5);
        mma_tile(t & 1);
    }

    __syncthreads();
    float* Csm = (float*)sm;
#pragma unroll
    for (int mf = 0; mf < 2; mf++)
#pragma unroll
        for (int nf = 0; nf < NF; nf++) {
            int r0 = wm * 32 + mf * 16, c0 = wn * WN + nf * 16;
            wmma::store_matrix_sync(Csm + r0 * 128 + c0, acc[mf][nf], 128, wmma::mem_row_major);
        }
    __syncthreads();

    const int NOUT = BM * 128 / 4 / 256;
#pragma unroll
    for (int i = 0; i < NOUT; i++) {
        int f = tid + i * 256;
        int row = f >> 5, c4 = (f & 31) * 4;
        float4 v = *(float4*)(Csm + row * 128 + c4);
        v.x *= alpha; v.y *= alpha; v.z *= alpha; v.w *= alpha;
        if (bias) {
            v.x += bias[n0 + c4 + 0]; v.y += bias[n0 + c4 + 1];
            v.z += bias[n0 + c4 + 2]; v.w += bias[n0 + c4 + 3];
        }
        long long o = coff + (long long)(m0 + row) * ldc + n0 + c4;
        if (Cf) {
            *(float4*)(Cf + o) = v;
        } else {
            __half x0, x1, y0, y1, z0, z1, w0, w1;
            split2(v.x, x0, x1); split2(v.y, y0, y1);
            split2(v.z, z0, z1); split2(v.w, w0, w1);
            __half2 p0 = __halves2half2(x0, y0), q0 = __halves2half2(z0, w0);
            *(uint2*)(C0g + o) = make_uint2(h2u(p0), h2u(q0));
            if (C1g) {
                __half2 p1 = __halves2half2(x1, y1), q1 = __halves2half2(z1, w1);
                *(uint2*)(C1g + o) = make_uint2(h2u(p1), h2u(q1));
            }
        }
    }
}

// ---------------------------------------------------------------------------
// Fused attention per (b, n) CTA:
//   S[64,256] = Q'@h^T (3-term) -> softmax -> P fp16 -> U[64,512] = P@h (1-term)
// smem (102400):
//   phase1 stage 2x51200 @0 | then Ssm fp32 64x264 @0, Psm0 @67584 (33792)
//   phase3 stage 2x16896 @0 | epilogue Csm fp32 64x264 @0
// ---------------------------------------------------------------------------
#define ATTN_SMEM 102400

__global__ __launch_bounds__(256) void k_attn() {
    extern __shared__ __align__(1024) char sm[];
    const int tid = threadIdx.x;
    const int w = tid >> 5, lane = tid & 31;
    const int wm = w & 1, wn = w >> 1;     // 2 x 4 warp grid, warp tile 32x64
    const int b = blockIdx.x, n = blockIdx.y;

    float* Ssm = (float*)sm;                               // 64 x 264 fp32
    __half* Psm0 = (__half*)(sm + 67584);                  // 64 x 264

    const __half* Qb0 = g_Q0 + ((size_t)n * 8192 + (size_t)b * 64) * 512;
    const __half* Qb1 = g_Q1 + ((size_t)n * 8192 + (size_t)b * 64) * 512;
    const __half* Hb0 = g_h0 + (size_t)b * 256 * 512;
    const __half* Hb1 = g_h1 + (size_t)b * 256 * 512;

    wmma::fragment<wmma::accumulator, 16, 16, 16, float> acc[2][4];
#pragma unroll
    for (int mf = 0; mf < 2; mf++)
#pragma unroll
        for (int nf = 0; nf < 4; nf++) wmma::fill_fragment(acc[mf][nf], 0.0f);

    // ======== phase 1: S = Q' @ h^T  (K=512, 16 chunks of 32, 3-term) =====
    {
        const int arow = tid >> 2, akc = (tid & 3) * 8;
        uint4 ra0, ra1, rb0[4], rb1[4];
        auto p1_load = [&](int k0) {
            ra0 = *(const uint4*)(Qb0 + (size_t)arow * 512 + k0 + akc);
            ra1 = *(const uint4*)(Qb1 + (size_t)arow * 512 + k0 + akc);
#pragma unroll
            for (int i = 0; i < 4; i++) {
                int id = tid + i * 256;
                int br = id >> 2, bkc = (id & 3) * 8;
                rb0[i] = *(const uint4*)(Hb0 + (size_t)br * 512 + k0 + bkc);
                rb1[i] = *(const uint4*)(Hb1 + (size_t)br * 512 + k0 + bkc);
            }
        };
        auto p1_store = [&](int buf) {
            char* base = sm + buf * 51200;
            __half* sA0 = (__half*)base;
            __half* sA1 = (__half*)(base + 5120);
            __half* sB0 = (__half*)(base + 10240);
            __half* sB1 = (__half*)(base + 30720);
            *(uint4*)(sA0 + arow * 40 + akc) = ra0;
            *(uint4*)(sA1 + arow * 40 + akc) = ra1;
#pragma unroll
            for (int i = 0; i < 4; i++) {
                int id = tid + i * 256;
                int br = id >> 2, bkc = (id & 3) * 8;
                *(uint4*)(sB0 + br * 40 + bkc) = rb0[i];
                *(uint4*)(sB1 + br * 40 + bkc) = rb1[i];
            }
        };
        auto p1_mma = [&](int buf) {
            const char* base = sm + buf * 51200;
            const __half* sA0 = (const __half*)base;
            const __half* sA1 = (const __half*)(base + 5120);
            const __half* sB0 = (const __half*)(base + 10240);
            const __half* sB1 = (const __half*)(base + 30720);
#pragma unroll
            for (int ks = 0; ks < 32; ks += 16) {
                wmma::fragment<wmma::matrix_a, 16, 16, 16, __half, wmma::row_major> a0f[2], a1f[2];
#pragma unroll
                for (int mf = 0; mf < 2; mf++) {
                    int r0 = wm * 32 + mf * 16;
                    wmma::load_matrix_sync(a0f[mf], sA0 + r0 * 40 + ks, 40);
                    wmma::load_matrix_sync(a1f[mf], sA1 + r0 * 40 + ks, 40);
                }
#pragma unroll
                for (int nf = 0; nf < 4; nf++) {
                    int col = wn * 64 + nf * 16;
                    wmma::fragment<wmma::matrix_b, 16, 16, 16, __half, wmma::col_major> b0f, b1f;
                    wmma::load_matrix_sync(b0f, sB0 + col * 40 + ks, 40);
                    wmma::load_matrix_sync(b1f, sB1 + col * 40 + ks, 40);
#pragma unroll
                    for (int mf = 0; mf < 2; mf++) {
                        wmma::mma_sync(acc[mf][nf], a0f[mf], b0f, acc[mf][nf]);
                        wmma::mma_sync(acc[mf][nf], a0f[mf], b1f, acc[mf][nf]);
                        wmma::mma_sync(acc[mf][nf], a1f[mf], b0f, acc[mf][nf]);
                    }
                }
            }
        };
        p1_load(0);
        for (int t = 0; t < 16; t++) {
            p1_store(t & 1);
            __syncthreads();
            if (t + 1 < 16) p1_load((t + 1) << 5);
            p1_mma(t & 1);
        }
    }

    // ======== stage S -> smem fp32 ========
    __syncthreads();
#pragma unroll
    for (int mf = 0; mf < 2; mf++)
#pragma unroll
        for (int nf = 0; nf < 4; nf++) {
            int r0 = wm * 32 + mf * 16, c0 = wn * 64 + nf * 16;
            wmma::store_matrix_sync(Ssm + r0 * 264 + c0, acc[mf][nf], 264, wmma::mem_row_major);
        }
    __syncthreads();

    // ======== softmax: warp w owns rows w*8 .. w*8+7; P fp16 single plane ==
#pragma unroll
    for (int i = 0; i < 8; i++) {
        int r = w * 8 + i;
        float* srow = Ssm + (size_t)r * 264 + lane * 8;
        float4 v0 = *(float4*)srow;
        float4 v1 = *(float4*)(srow + 4);
        float m = fmaxf(fmaxf(fmaxf(v0.x, v0.y), fmaxf(v0.z, v0.w)),
                        fmaxf(fmaxf(v1.x, v1.y), fmaxf(v1.z, v1.w)));
#pragma unroll
        for (int off = 16; off > 0; off >>= 1)
            m = fmaxf(m, __shfl_xor_sync(0xffffffffu, m, off));
        v0.x = __expf(v0.x - m); v0.y = __expf(v0.y - m);
        v0.z = __expf(v0.z - m); v0.w = __expf(v0.w - m);
        v1.x = __expf(v1.x - m); v1.y = __expf(v1.y - m);
        v1.z = __expf(v1.z - m); v1.w = __expf(v1.w - m);
        float s = v0.x + v0.y + v0.z + v0.w + v1.x + v1.y + v1.z + v1.w;
#pragma unroll
        for (int off = 16; off > 0; off >>= 1)
            s += __shfl_xor_sync(0xffffffffu, s, off);
        const float inv = 1.0f / s;
        __align__(16) __half h0[8];
        h0[0] = __float2half_rn(v0.x * inv); h0[1] = __float2half_rn(v0.y * inv);
        h0[2] = __float2half_rn(v0.z * inv); h0[3] = __float2half_rn(v0.w * inv);
        h0[4] = __float2half_rn(v1.x * inv); h0[5] = __float2half_rn(v1.y * inv);
        h0[6] = __float2half_rn(v1.z * inv); h0[7] = __float2half_rn(v1.w * inv);
        *(uint4*)(Psm0 + (size_t)r * 264 + lane * 8) = *(uint4*)h0;
    }
    __syncthreads();

    // ======== phase 3: U = P @ h  (1-term; two 256-col halves; K=256) =====
    for (int hh = 0; hh < 2; hh++) {
        const int d0 = hh * 256;
#pragma unroll
        for (int mf = 0; mf < 2; mf++)
#pragma unroll
            for (int nf = 0; nf < 4; nf++) wmma::fill_fragment(acc[mf][nf], 0.0f);

        uint4 rh0[4];
        auto p3_load = [&](int k0) {
#pragma unroll
            for (int i = 0; i < 4; i++) {
                int id = tid + i * 256;
                int er = id >> 5, dc = id & 31;
                rh0[i] = *(const uint4*)(Hb0 + (size_t)(k0 + er) * 512 + d0 + dc * 8);
            }
        };
        auto p3_store = [&](int buf) {
            __half* sH0 = (__half*)(sm + buf * 16896);
#pragma unroll
            for (int i = 0; i < 4; i++) {
                int id = tid + i * 256;
                int er = id >> 5, dc = id & 31;
                *(uint4*)(sH0 + er * 264 + dc * 8) = rh0[i];
            }
        };
        auto p3_mma = [&](int buf, int c) {
            const __half* sH0 = (const __half*)(sm + buf * 16896);
#pragma unroll
            for (int ks = 0; ks < 32; ks += 16) {
                wmma::fragment<wmma::matrix_a, 16, 16, 16, __half, wmma::row_major> a0f[2];
#pragma unroll
                for (int mf = 0; mf < 2; mf++) {
                    int r0 = wm * 32 + mf * 16;
                    wmma::load_matrix_sync(a0f[mf], Psm0 + r0 * 264 + c * 32 + ks, 264);
                }
#pragma unroll
                for (int nf = 0; nf < 4; nf++) {
                    int col = wn * 64 + nf * 16;
                    wmma::fragment<wmma::matrix_b, 16, 16, 16, __half, wmma::row_major> b0f;
                    wmma::load_matrix_sync(b0f, sH0 + ks * 264 + col, 264);
#pragma unroll
                    for (int mf = 0; mf < 2; mf++)
                        wmma::mma_sync(acc[mf][nf], a0f[mf], b0f, acc[mf][nf]);
                }
            }
        };
        p3_load(0);
        for (int c = 0; c < 8; c++) {
            p3_store(c & 1);
            __syncthreads();
            if (c + 1 < 8) p3_load((c + 1) << 5);
            p3_mma(c & 1, c);
        }

        __syncthreads();
        float* Csm = (float*)sm;
#pragma unroll
        for (int mf = 0; mf < 2; mf++)
#pragma unroll
            for (int nf = 0; nf < 4; nf++) {
                int r0 = wm * 32 + mf * 16, c0 = wn * 64 + nf * 16;
                wmma::store_matrix_sync(Csm + r0 * 264 + c0, acc[mf][nf], 264, wmma::mem_row_major);
            }
        __syncthreads();
#pragma unroll
        for (int i = 0; i < 16; i++) {
            int id = tid + i * 256;
            int row = id >> 6, c4 = (id & 63) * 4;
            float4 v = *(float4*)(Csm + row * 264 + c4);
            __align__(8) __half h4[4];
            h4[0] = __float2half_rn(v.x); h4[1] = __float2half_rn(v.y);
            h4[2] = __float2half_rn(v.z); h4[3] = __float2half_rn(v.w);
            size_t o = (((size_t)(b * 64 + row)) * 8 + n) * 512 + d0 + c4;
            *(uint2*)(g_U0 + o) = *(uint2*)h4;
        }
        __syncthreads();
    }
}

// ---------------------------------------------------------------------------
extern "C" void kernel_launch(void* const* d_in, const int* in_sizes, int n_in,
                              void* d_out, int out_size) {
    const float* x     = (const float*)d_in[0];
    const float* W_enc = (const float*)d_in[1];
    const float* b_enc = (const float*)d_in[2];
    const float* WQ    = (const float*)d_in[3];
    const float* WK    = (const float*)d_in[4];
    const float* WV    = (const float*)d_in[5];
    float* out = (float*)d_out;

    const int SM128_3 = 2 * 2 * (128 * 40 * 2 + 128 * 40 * 2);   // 81920
    // NT=1 stage is 40960 B, but the fp32 C epilogue staging needs 128*128*4:
    const int SM128_1 = 128 * 128 * 4;                            // 65536
    cudaFuncSetAttribute(k_mma<128, 3>, cudaFuncAttributeMaxDynamicSharedMemorySize, SM128_3);
    cudaFuncSetAttribute(k_mma<128, 1>, cudaFuncAttributeMaxDynamicSharedMemorySize, SM128_1);
    cudaFuncSetAttribute(k_attn, cudaFuncAttributeMaxDynamicSharedMemorySize, ATTN_SMEM);

    void *p_M, *p_h0, *p_h1, *p_Q0, *p_Q1, *p_U0;
    void *p_e0, *p_e1, *p_m0, *p_m1, *p_w0, *p_w1, *p_k0, *p_k1;
    cudaGetSymbolAddress(&p_M, g_M);
    cudaGetSymbolAddress(&p_h0, g_h0); cudaGetSymbolAddress(&p_h1, g_h1);
    cudaGetSymbolAddress(&p_Q0, g_Q0); cudaGetSymbolAddress(&p_Q1, g_Q1);
    cudaGetSymbolAddress(&p_U0, g_U0);
    cudaGetSymbolAddress(&p_e0, g_Te0); cudaGetSymbolAddress(&p_e1, g_Te1);
    cudaGetSymbolAddress(&p_m0, g_Tm0); cudaGetSymbolAddress(&p_m1, g_Tm1);
    cudaGetSymbolAddress(&p_w0, g_Tw0); cudaGetSymbolAddress(&p_w1, g_Tw1);
    cudaGetSymbolAddress(&p_k0, g_Wk0); cudaGetSymbolAddress(&p_k1, g_Wk1);

    // ---- weight prep
    k_tsplit2<<<dim3(8, 16, 1), dim3(32, 8)>>>(W_enc, (__half*)p_e0, (__half*)p_e1, 256, 512);
    k_tsplit2<<<dim3(128, 16, 1), dim3(32, 8)>>>(WV, (__half*)p_w0, (__half*)p_w1, 4096, 512);
    k_split2e<<<dim3(512), 256>>>(WK, (__half*)p_k0, (__half*)p_k1, (size_t)8 * 512 * 512);

    // ---- M_n = (WQ_n @ WK_n^T) * scale   (WMMA 3-term; WK is already [N,K])
    k_mma<128, 3><<<dim3(4, 4, 8), 256, SM128_3>>>(
        WQ, nullptr, nullptr, (const __half*)p_k0, (const __half*)p_k1,
        (float*)p_M, nullptr, nullptr, nullptr, 0.04419417382415922f,
        512, 512, 512, 512, /*flags*/0,
        (long long)512 * 512, (long long)512 * 512, (long long)512 * 512);

    k_tsplit2<<<dim3(16, 16, 8), dim3(32, 8)>>>((const float*)p_M, (__half*)p_m0, (__half*)p_m1, 512, 512);

    // ---- encode: h planes = lrelu(x) @ W_enc + b
    k_mma<128, 3><<<dim3(4, 256, 1), 256, SM128_3>>>(
        x, nullptr, nullptr, (const __half*)p_e0, (const __half*)p_e1,
        nullptr, (__half*)p_h0, (__half*)p_h1, b_enc, 1.0f,
        256, 256, 256, 512, /*flags*/1, 0, 0, 0);

    // ---- Q' planes = ha @ M_n   (gather, batched over heads)
    k_mma<128, 3><<<dim3(4, 64, 8), 256, SM128_3>>>(
        nullptr, (const __half*)p_h0, (const __half*)p_h1,
        (const __half*)p_m0, (const __half*)p_m1,
        nullptr, (__half*)p_Q0, (__half*)p_Q1, nullptr, 1.0f,
        512, 512, 512, 512, /*flags*/2,
        0, (long long)512 * 512, (long long)8192 * 512);

    // ---- fused attention (S 3-term -> softmax -> U 1-term fp16)
    k_attn<<<dim3(128, 8), 256, ATTN_SMEM>>>();

    // ---- out = (1/8) U @ WVcat   (1-term fp16)
    k_mma<128, 1><<<dim3(4, 64, 1), 256, SM128_1>>>(
        nullptr, (const __half*)p_U0, nullptr,
        (const __half*)p_w0, nullptr,
        out, nullptr, nullptr, nullptr, 0.125f,
        4096, 4096, 4096, 512, 0, 0, 0, 0);
}